// round 3
// baseline (speedup 1.0000x reference)
#include <cuda_runtime.h>
#include <math.h>

#define B_        32
#define N_NODE    200
#define N_REL     34
#define C_DIM     200
#define C_IN      1024
#define SENT_DIM  1024
#define FC_DIM    512
#define NBR       (B_ * N_REL)          /* 1088 */
#define NN        (N_NODE * N_NODE)     /* 40000 */
#define LAYER_W   (N_REL * C_DIM * C_DIM) /* 1,360,000 */
#define GNW_ELEMS (3 * C_DIM * C_DIM * N_REL) /* 4,080,000 */

// -------- device scratch (no allocations allowed) --------
__device__ float g_x  [B_ * N_NODE * C_DIM];
__device__ float g_x2 [B_ * N_NODE * C_DIM];
__device__ float g_z  [(size_t)NBR * NN];     // 174 MB: per-(b,r) aggregated features
__device__ float g_inv[NBR * N_NODE];
__device__ float g_W2 [3 * LAYER_W];          // gnn_w transposed: [l][r][c][o]
__device__ float g_k  [B_ * N_NODE * C_DIM];
__device__ float g_v  [B_ * N_NODE * C_DIM];
__device__ float g_q  [B_ * C_DIM];
__device__ float g_gv [B_ * C_DIM];

__device__ __forceinline__ float gelu_f(float x) {
    return 0.5f * x * (1.0f + erff(x * 0.70710678118654752f));
}

#define MM16(A4, B4) do { \
    acc[0][0] += A4.x * B4.x; acc[0][1] += A4.x * B4.y; acc[0][2] += A4.x * B4.z; acc[0][3] += A4.x * B4.w; \
    acc[1][0] += A4.y * B4.x; acc[1][1] += A4.y * B4.y; acc[1][2] += A4.y * B4.z; acc[1][3] += A4.y * B4.w; \
    acc[2][0] += A4.z * B4.x; acc[2][1] += A4.z * B4.y; acc[2][2] += A4.z * B4.z; acc[2][3] += A4.z * B4.w; \
    acc[3][0] += A4.w * B4.x; acc[3][1] += A4.w * B4.y; acc[3][2] += A4.w * B4.z; acc[3][3] += A4.w * B4.w; \
} while (0)

// ---------------------------------------------------------------------------
// inv degree: invdeg[b,r,i] = 1 / max(sum_k adj[b,r,k,i], 1)
// ---------------------------------------------------------------------------
__global__ void k_deg(const float* __restrict__ adj, float* __restrict__ invdeg) {
    int br = blockIdx.x;
    int t = threadIdx.x;
    if (t < N_NODE) {
        const float* a = adj + (size_t)br * NN + t;
        float s = 0.f;
        #pragma unroll 4
        for (int k = 0; k < N_NODE; k++) s += a[(size_t)k * N_NODE];
        invdeg[br * N_NODE + t] = 1.0f / fmaxf(s, 1.0f);
    }
}

// ---------------------------------------------------------------------------
// transpose gnn_w: W2[l][r][c][o] = gnn_w[l][c][o*R + r]
// ---------------------------------------------------------------------------
__global__ void k_w2(const float* __restrict__ gw, float* __restrict__ w2) {
    int idx = blockIdx.x * 256 + threadIdx.x;
    if (idx >= GNW_ELEMS) return;
    int l = idx / (C_DIM * C_DIM * N_REL);
    int rem = idx % (C_DIM * C_DIM * N_REL);
    int c = rem / (C_DIM * N_REL);
    int q = rem % (C_DIM * N_REL);
    int o = q / N_REL;
    int r = q % N_REL;
    w2[(((size_t)l * N_REL + r) * C_DIM + c) * C_DIM + o] = gw[idx];
}

// ---------------------------------------------------------------------------
// Generic tiled GEMM: C[M,N] = act(A[M,K] @ B[K,N] + bias), A optionally gathered.
// 64x64x16 tiles, 256 threads, 4x4 microtiles.
// ---------------------------------------------------------------------------
template <bool GELU>
__global__ void k_gemm(const float* __restrict__ A, const int* __restrict__ gather, int lda,
                       const float* __restrict__ Bm, const float* __restrict__ bias,
                       float* __restrict__ C, int M, int N, int K) {
    __shared__ __align__(16) float sA[16][68];   // [k][m], +4 pad (row stride 272B, 16B aligned)
    __shared__ __align__(16) float sB[16][64];   // [k][n]
    int t = threadIdx.x;
    int n0 = blockIdx.x * 64, m0 = blockIdx.y * 64;
    int tr = t >> 4, tc = t & 15;
    int mmA = t >> 2, kqA = (t & 3) * 4;
    int kkB = t >> 4, nqB = (t & 15) * 4;

    int gm = m0 + mmA;
    const float* arow = nullptr;
    if (gm < M) arow = A + (size_t)(gather ? gather[gm] : gm) * lda;

    float acc[4][4] = {};
    for (int k0 = 0; k0 < K; k0 += 16) {
        float4 av = make_float4(0.f, 0.f, 0.f, 0.f);
        int ka = k0 + kqA;
        if (arow && ka < K) av = *reinterpret_cast<const float4*>(arow + ka);
        float4 bv = make_float4(0.f, 0.f, 0.f, 0.f);
        int kb = k0 + kkB;
        if (kb < K && n0 + nqB < N)
            bv = *reinterpret_cast<const float4*>(Bm + (size_t)kb * N + n0 + nqB);
        __syncthreads();
        sA[kqA + 0][mmA] = av.x; sA[kqA + 1][mmA] = av.y;
        sA[kqA + 2][mmA] = av.z; sA[kqA + 3][mmA] = av.w;
        *reinterpret_cast<float4*>(&sB[kkB][nqB]) = bv;
        __syncthreads();
        #pragma unroll
        for (int kk = 0; kk < 16; kk++) {
            float4 a4 = *reinterpret_cast<const float4*>(&sA[kk][tr * 4]);
            float4 b4 = *reinterpret_cast<const float4*>(&sB[kk][tc * 4]);
            MM16(a4, b4);
        }
    }
    #pragma unroll
    for (int i = 0; i < 4; i++) {
        int m = m0 + tr * 4 + i;
        if (m >= M) continue;
        #pragma unroll
        for (int j = 0; j < 4; j++) {
            int n = n0 + tc * 4 + j;
            if (n >= N) continue;
            float v = acc[i][j] + bias[n];
            if (GELU) v = gelu_f(v);
            C[(size_t)m * N + n] = v;
        }
    }
}

// ---------------------------------------------------------------------------
// Aggregate: z[b,r][i][c] = invdeg[b,r,i] * sum_j adj[b,r][j][i] * x[b][j][c]
// (A^T GEMM — transpose is free: both tiles are loaded K-row-contiguous.)
// ---------------------------------------------------------------------------
__global__ void k_agg(const float* __restrict__ adj, const float* __restrict__ xin,
                      const float* __restrict__ invdeg, float* __restrict__ z) {
    __shared__ __align__(16) float sA[16][64];   // [j][i]
    __shared__ __align__(16) float sX[16][64];   // [j][c]
    int br = blockIdx.z;
    int b = br / N_REL;
    int i0 = blockIdx.y * 64, c0 = blockIdx.x * 64;
    const float* Ab = adj + (size_t)br * NN;
    const float* Xb = xin + (size_t)b * NN;
    int t = threadIdx.x;
    int tr = t >> 4, tc = t & 15;
    int kk = t >> 4, q4 = (t & 15) * 4;

    float acc[4][4] = {};
    for (int j0 = 0; j0 < N_NODE; j0 += 16) {
        float4 av = make_float4(0.f, 0.f, 0.f, 0.f);
        float4 xv = make_float4(0.f, 0.f, 0.f, 0.f);
        int j = j0 + kk;
        if (j < N_NODE) {
            if (i0 + q4 < N_NODE) av = *reinterpret_cast<const float4*>(Ab + (size_t)j * N_NODE + i0 + q4);
            if (c0 + q4 < N_NODE) xv = *reinterpret_cast<const float4*>(Xb + (size_t)j * C_DIM + c0 + q4);
        }
        __syncthreads();
        *reinterpret_cast<float4*>(&sA[kk][q4]) = av;
        *reinterpret_cast<float4*>(&sX[kk][q4]) = xv;
        __syncthreads();
        #pragma unroll
        for (int k2 = 0; k2 < 16; k2++) {
            float4 a4 = *reinterpret_cast<const float4*>(&sA[k2][tr * 4]);
            float4 b4 = *reinterpret_cast<const float4*>(&sX[k2][tc * 4]);
            MM16(a4, b4);
        }
    }
    #pragma unroll
    for (int i = 0; i < 4; i++) {
        int ii = i0 + tr * 4 + i;
        if (ii >= N_NODE) continue;
        float sc = invdeg[br * N_NODE + ii];
        #pragma unroll
        for (int j = 0; j < 4; j++) {
            int cc = c0 + tc * 4 + j;
            if (cc >= C_DIM) continue;
            z[((size_t)br * N_NODE + ii) * C_DIM + cc] = acc[i][j] * sc;
        }
    }
}

// ---------------------------------------------------------------------------
// Mix: xout[b][i][o] = gelu( sum_r  z[b,r][i][:] @ W2l[r][:][o] )
// ---------------------------------------------------------------------------
__global__ void k_mix(const float* __restrict__ z, const float* __restrict__ W2l,
                      float* __restrict__ xout) {
    __shared__ __align__(16) float sA[16][68];
    __shared__ __align__(16) float sB[16][64];
    int b = blockIdx.z;
    int i0 = blockIdx.y * 64, o0 = blockIdx.x * 64;
    int t = threadIdx.x;
    int tr = t >> 4, tc = t & 15;
    int mmA = t >> 2, kqA = (t & 3) * 4;
    int kkB = t >> 4, nqB = (t & 15) * 4;

    float acc[4][4] = {};
    for (int r = 0; r < N_REL; r++) {
        const float* Zr = z + ((size_t)(b * N_REL + r)) * NN;
        const float* Wr = W2l + (size_t)r * (C_DIM * C_DIM);
        for (int kc = 0; kc < C_DIM; kc += 16) {
            float4 av = make_float4(0.f, 0.f, 0.f, 0.f);
            int ka = kc + kqA;
            if (i0 + mmA < N_NODE && ka < C_DIM)
                av = *reinterpret_cast<const float4*>(Zr + (size_t)(i0 + mmA) * C_DIM + ka);
            float4 bv = make_float4(0.f, 0.f, 0.f, 0.f);
            int kb = kc + kkB;
            if (kb < C_DIM && o0 + nqB < C_DIM)
                bv = *reinterpret_cast<const float4*>(Wr + (size_t)kb * C_DIM + o0 + nqB);
            __syncthreads();
            sA[kqA + 0][mmA] = av.x; sA[kqA + 1][mmA] = av.y;
            sA[kqA + 2][mmA] = av.z; sA[kqA + 3][mmA] = av.w;
            *reinterpret_cast<float4*>(&sB[kkB][nqB]) = bv;
            __syncthreads();
            #pragma unroll
            for (int kk = 0; kk < 16; kk++) {
                float4 a4 = *reinterpret_cast<const float4*>(&sA[kk][tr * 4]);
                float4 b4 = *reinterpret_cast<const float4*>(&sB[kk][tc * 4]);
                MM16(a4, b4);
            }
        }
    }
    #pragma unroll
    for (int i = 0; i < 4; i++) {
        int ii = i0 + tr * 4 + i;
        if (ii >= N_NODE) continue;
        #pragma unroll
        for (int j = 0; j < 4; j++) {
            int oo = o0 + tc * 4 + j;
            if (oo >= C_DIM) continue;
            xout[(size_t)b * NN + (size_t)ii * C_DIM + oo] = gelu_f(acc[i][j]);
        }
    }
}

// ---------------------------------------------------------------------------
// Attention pooling: one block per b. Writes pool_attn into d_out and graph_vecs.
// ---------------------------------------------------------------------------
__global__ void k_attn(const float* __restrict__ q, const float* __restrict__ ks,
                       const float* __restrict__ vs, const int* __restrict__ lens,
                       float* __restrict__ out, float* __restrict__ gv) {
    int b = blockIdx.x;
    int t = threadIdx.x;   // 256
    __shared__ float sq[C_DIM];
    __shared__ float sa[2][N_NODE];
    __shared__ float red[256];
    if (t < C_DIM) sq[t] = q[b * C_DIM + t];
    __syncthreads();
    int len = lens[b];
    for (int h = 0; h < 2; h++) {
        float s = -INFINITY;
        if (t < N_NODE && t < len) {
            float acc = 0.f;
            const float* kr = ks + ((size_t)(b * N_NODE + t)) * C_DIM + h * 100;
            #pragma unroll 4
            for (int d = 0; d < 100; d++) acc += sq[h * 100 + d] * kr[d];
            s = acc * 0.1f;   // / sqrt(dk=100)
        }
        red[t] = s;
        __syncthreads();
        for (int off = 128; off > 0; off >>= 1) {
            if (t < off) red[t] = fmaxf(red[t], red[t + off]);
            __syncthreads();
        }
        float mx = red[0];
        __syncthreads();
        float e = (t < N_NODE && t < len) ? expf(s - mx) : 0.f;
        red[t] = e;
        __syncthreads();
        for (int off = 128; off > 0; off >>= 1) {
            if (t < off) red[t] += red[t + off];
            __syncthreads();
        }
        float inv = 1.f / red[0];
        __syncthreads();
        if (t < N_NODE) {
            float a = e * inv;
            sa[h][t] = a;
            // pool_attn row = h*B + b
            out[32 + ((size_t)(h * B_ + b)) * N_NODE + t] = a;
        }
        __syncthreads();
    }
    if (t < C_DIM) {
        int h = t / 100, d = t % 100;
        float g = 0.f;
        for (int l = 0; l < N_NODE; l++)
            g += sa[h][l] * vs[((size_t)(b * N_NODE + l)) * C_DIM + h * 100 + d];
        gv[b * C_DIM + t] = g;
    }
}

// ---------------------------------------------------------------------------
// MLP readout: one block (512 threads) per b.
// ---------------------------------------------------------------------------
__global__ void k_mlp(const float* __restrict__ gv, const float* __restrict__ sent,
                      const float* __restrict__ W0, const float* __restrict__ b0,
                      const float* __restrict__ lng, const float* __restrict__ lnb,
                      const float* __restrict__ W1, const float* __restrict__ b1,
                      float* __restrict__ out) {
    int b = blockIdx.x;
    int t = threadIdx.x;   // 512
    const int ZD = C_DIM + SENT_DIM;   // 1224
    __shared__ float zz[C_DIM + SENT_DIM];
    __shared__ float red[512];
    for (int i = t; i < ZD; i += 512)
        zz[i] = (i < C_DIM) ? gv[b * C_DIM + i] : sent[(size_t)b * SENT_DIM + (i - C_DIM)];
    __syncthreads();
    float acc = b0[t];
    #pragma unroll 4
    for (int k = 0; k < ZD; k++) acc += zz[k] * W0[(size_t)k * FC_DIM + t];
    // mean
    red[t] = acc; __syncthreads();
    for (int off = 256; off > 0; off >>= 1) { if (t < off) red[t] += red[t + off]; __syncthreads(); }
    float mu = red[0] * (1.f / FC_DIM);
    __syncthreads();
    float d = acc - mu;
    red[t] = d * d; __syncthreads();
    for (int off = 256; off > 0; off >>= 1) { if (t < off) red[t] += red[t + off]; __syncthreads(); }
    float var = red[0] * (1.f / FC_DIM);
    __syncthreads();
    float h1 = gelu_f(d * rsqrtf(var + 1e-5f) * lng[t] + lnb[t]);
    red[t] = h1 * W1[t]; __syncthreads();
    for (int off = 256; off > 0; off >>= 1) { if (t < off) red[t] += red[t + off]; __syncthreads(); }
    if (t == 0) out[b] = red[0] + b1[0];
}

// ---------------------------------------------------------------------------
extern "C" void kernel_launch(void* const* d_in, const int* in_sizes, int n_in,
                              void* d_out, int out_size) {
    const float* sent     = (const float*)d_in[0];
    const int*   concepts = (const int*)  d_in[1];
    const float* adj      = (const float*)d_in[2];
    const int*   lens     = (const int*)  d_in[3];
    const float* emb      = (const float*)d_in[4];
    const float* cptW     = (const float*)d_in[5];
    const float* cptb     = (const float*)d_in[6];
    const float* gnnw     = (const float*)d_in[7];
    const float* wq       = (const float*)d_in[8];
    const float* bq       = (const float*)d_in[9];
    const float* wk       = (const float*)d_in[10];
    const float* bk       = (const float*)d_in[11];
    const float* wv       = (const float*)d_in[12];
    const float* bv       = (const float*)d_in[13];
    const float* fcW0     = (const float*)d_in[14];
    const float* fcb0     = (const float*)d_in[15];
    const float* lng      = (const float*)d_in[16];
    const float* lnb      = (const float*)d_in[17];
    const float* fcW1     = (const float*)d_in[18];
    const float* fcb1     = (const float*)d_in[19];
    float* out = (float*)d_out;

    float *px, *px2, *pz, *pinv, *pw2, *pk, *pv, *pq, *pgv;
    cudaGetSymbolAddress((void**)&px,   g_x);
    cudaGetSymbolAddress((void**)&px2,  g_x2);
    cudaGetSymbolAddress((void**)&pz,   g_z);
    cudaGetSymbolAddress((void**)&pinv, g_inv);
    cudaGetSymbolAddress((void**)&pw2,  g_W2);
    cudaGetSymbolAddress((void**)&pk,   g_k);
    cudaGetSymbolAddress((void**)&pv,   g_v);
    cudaGetSymbolAddress((void**)&pq,   g_q);
    cudaGetSymbolAddress((void**)&pgv,  g_gv);

    // degree + weight transpose
    k_deg<<<NBR, 256>>>(adj, pinv);
    k_w2<<<(GNW_ELEMS + 255) / 256, 256>>>(gnnw, pw2);

    // embedding: x = gelu(emb[concepts] @ cpt_W + cpt_b)   (M=6400, K=1024, N=200)
    {
        dim3 g((C_DIM + 63) / 64, (B_ * N_NODE + 63) / 64);
        k_gemm<true><<<g, 256>>>(emb, concepts, C_IN, cptW, cptb, px,
                                 B_ * N_NODE, C_DIM, C_IN);
    }

    dim3 gAgg((C_DIM + 63) / 64, (N_NODE + 63) / 64, NBR);
    dim3 gMix((C_DIM + 63) / 64, (N_NODE + 63) / 64, B_);

    // 3 RGCN layers, ping-pong x buffers
    k_agg<<<gAgg, 256>>>(adj, px, pinv, pz);
    k_mix<<<gMix, 256>>>(pz, pw2 + (size_t)0 * LAYER_W, px2);
    k_agg<<<gAgg, 256>>>(adj, px2, pinv, pz);
    k_mix<<<gMix, 256>>>(pz, pw2 + (size_t)1 * LAYER_W, px);
    k_agg<<<gAgg, 256>>>(adj, px, pinv, pz);
    k_mix<<<gMix, 256>>>(pz, pw2 + (size_t)2 * LAYER_W, px2);   // final x in px2

    // q = sent @ wq + bq  (M=32, K=1024, N=200)
    {
        dim3 g((C_DIM + 63) / 64, (B_ + 63) / 64);
        k_gemm<false><<<g, 256>>>(sent, nullptr, SENT_DIM, wq, bq, pq, B_, C_DIM, SENT_DIM);
    }
    // k/v = x @ wk/wv + b  (M=6400, K=200, N=200)
    {
        dim3 g((C_DIM + 63) / 64, (B_ * N_NODE + 63) / 64);
        k_gemm<false><<<g, 256>>>(px2, nullptr, C_DIM, wk, bk, pk, B_ * N_NODE, C_DIM, C_DIM);
        k_gemm<false><<<g, 256>>>(px2, nullptr, C_DIM, wv, bv, pv, B_ * N_NODE, C_DIM, C_DIM);
    }

    // attention pooling (writes pool_attn part of out) + graph_vecs
    k_attn<<<B_, 256>>>(pq, pk, pv, lens, out, pgv);

    // MLP readout (writes logits part of out)
    k_mlp<<<B_, 512>>>(pgv, sent, fcW0, fcb0, lng, lnb, fcW1, fcb1, out);
}

// round 4
// speedup vs baseline: 1.4048x; 1.4048x over previous
#include <cuda_runtime.h>
#include <math.h>
#include <stdint.h>

#define B_        32
#define N_NODE    200
#define N_REL     34
#define C_DIM     200
#define C_IN      1024
#define SENT_DIM  1024
#define FC_DIM    512
#define NBR_      (B_ * N_REL)            /* 1088 */
#define NN        (N_NODE * N_NODE)       /* 40000 */
#define RC        (N_REL * C_DIM)         /* 6800 */
#define ROWS      (B_ * N_NODE)           /* 6400 */

// -------- device scratch (no allocations allowed) --------
__device__ float   g_x  [ROWS * C_DIM];
__device__ float   g_x2 [ROWS * C_DIM];
__device__ float   g_y  [(size_t)ROWS * RC];    // 174 MB: y[b*200+j][r*200+o]
__device__ float   g_W2 [3 * C_DIM * RC];       // W2[l][c][r*200+o]
__device__ uint8_t g_nbr[(size_t)NBR_ * N_NODE * N_NODE]; // padded in-neighbor lists
__device__ int     g_cnt[NBR_ * N_NODE];
__device__ float   g_k  [ROWS * C_DIM];
__device__ float   g_v  [ROWS * C_DIM];
__device__ float   g_q  [B_ * C_DIM];
__device__ float   g_gv [B_ * C_DIM];

__device__ __forceinline__ float gelu_f(float x) {
    return 0.5f * x * (1.0f + erff(x * 0.70710678118654752f));
}

// ---------------------------------------------------------------------------
// Build in-edge lists: nbr[br][i][*] = { j : adj[br][j][i] != 0 },  cnt = count.
// Binary adjacency => degree == cnt (>=1 thanks to self loops).
// ---------------------------------------------------------------------------
__global__ void k_build(const float* __restrict__ adj, uint8_t* __restrict__ nbr,
                        int* __restrict__ cnt) {
    int br = blockIdx.x;
    int i = threadIdx.x;
    if (i < N_NODE) {
        const float* a = adj + (size_t)br * NN + i;
        uint8_t* nb = nbr + ((size_t)br * N_NODE + i) * N_NODE;
        int c = 0;
        for (int j = 0; j < N_NODE; j++)
            if (a[(size_t)j * N_NODE] != 0.f) nb[c++] = (uint8_t)j;
        cnt[br * N_NODE + i] = c;
    }
}

// ---------------------------------------------------------------------------
// Permute gnn_w rows: w2[l][c][r*200+o] = gw[l][c][o*34+r].  One block per (l,c).
// ---------------------------------------------------------------------------
__global__ void k_w2t(const float* __restrict__ gw, float* __restrict__ w2) {
    __shared__ float s[RC];
    int lc = blockIdx.x;                       // 0..599
    const float* src = gw + (size_t)lc * RC;
    float* dst = w2 + (size_t)lc * RC;
    for (int idx = threadIdx.x; idx < RC; idx += 256) s[idx] = src[idx];
    __syncthreads();
    for (int n = threadIdx.x; n < RC; n += 256) {
        int r = n / C_DIM, o = n % C_DIM;
        dst[n] = s[o * N_REL + r];
    }
}

// ---------------------------------------------------------------------------
// Tiled GEMM: C[M,N] = act(A[M,K] @ B[K,N] + bias), A optionally row-gathered.
// 64(M) x 128(N) x 16(K) tiles, 256 threads, 4x8 microtiles.
// Requires K % 4 == 0, N % 8 == 0 (holds for all call sites).
// ---------------------------------------------------------------------------
template <bool GELU, bool BIAS>
__global__ void k_gemm(const float* __restrict__ A, const int* __restrict__ gather, int lda,
                       const float* __restrict__ Bm, int ldb, const float* __restrict__ bias,
                       float* __restrict__ C, int ldc, int M, int N, int K) {
    __shared__ __align__(16) float sA[16][68];   // [k][m] (+4 pad)
    __shared__ __align__(16) float sB[16][128];  // [k][n]
    int t = threadIdx.x;
    int n0 = blockIdx.x * 128, m0 = blockIdx.y * 64;
    int tr = t >> 4, tc = t & 15;
    int mmA = t >> 2, kqA = (t & 3) * 4;
    int kkB = t >> 4, nqB = (t & 15) * 8;

    int gm = m0 + mmA;
    const float* arow = nullptr;
    if (gm < M) arow = A + (size_t)(gather ? gather[gm] : gm) * lda;

    float acc[4][8] = {};
    for (int k0 = 0; k0 < K; k0 += 16) {
        float4 av = make_float4(0.f, 0.f, 0.f, 0.f);
        int ka = k0 + kqA;
        if (arow && ka < K) av = *reinterpret_cast<const float4*>(arow + ka);
        float4 bv0 = make_float4(0.f, 0.f, 0.f, 0.f);
        float4 bv1 = make_float4(0.f, 0.f, 0.f, 0.f);
        int kb = k0 + kkB;
        if (kb < K && n0 + nqB < N) {
            const float* bp = Bm + (size_t)kb * ldb + n0 + nqB;
            bv0 = *reinterpret_cast<const float4*>(bp);
            bv1 = *reinterpret_cast<const float4*>(bp + 4);
        }
        __syncthreads();
        sA[kqA + 0][mmA] = av.x; sA[kqA + 1][mmA] = av.y;
        sA[kqA + 2][mmA] = av.z; sA[kqA + 3][mmA] = av.w;
        *reinterpret_cast<float4*>(&sB[kkB][nqB])     = bv0;
        *reinterpret_cast<float4*>(&sB[kkB][nqB + 4]) = bv1;
        __syncthreads();
        #pragma unroll
        for (int kk = 0; kk < 16; kk++) {
            float4 a4 = *reinterpret_cast<const float4*>(&sA[kk][tr * 4]);
            float4 b0 = *reinterpret_cast<const float4*>(&sB[kk][tc * 8]);
            float4 b1 = *reinterpret_cast<const float4*>(&sB[kk][tc * 8 + 4]);
            const float am[4] = {a4.x, a4.y, a4.z, a4.w};
            #pragma unroll
            for (int i = 0; i < 4; i++) {
                acc[i][0] += am[i] * b0.x; acc[i][1] += am[i] * b0.y;
                acc[i][2] += am[i] * b0.z; acc[i][3] += am[i] * b0.w;
                acc[i][4] += am[i] * b1.x; acc[i][5] += am[i] * b1.y;
                acc[i][6] += am[i] * b1.z; acc[i][7] += am[i] * b1.w;
            }
        }
    }
    #pragma unroll
    for (int i = 0; i < 4; i++) {
        int m = m0 + tr * 4 + i;
        if (m >= M) continue;
        #pragma unroll
        for (int j = 0; j < 8; j++) {
            int n = n0 + tc * 8 + j;
            if (n >= N) continue;
            float v = acc[i][j];
            if (BIAS) v += bias[n];
            if (GELU) v = gelu_f(v);
            C[(size_t)m * ldc + n] = v;
        }
    }
}

// ---------------------------------------------------------------------------
// Sparse aggregate + GELU:
// xout[b,i,o] = gelu( sum_r (1/cnt[b,r,i]) * sum_{j in nbr(b,r,i)} y[b,j, r*200+o] )
// One block per (b,i); threads = o.
// ---------------------------------------------------------------------------
__global__ void k_sagg(const float* __restrict__ y, const uint8_t* __restrict__ nbr,
                       const int* __restrict__ cnt, float* __restrict__ xout) {
    int bi = blockIdx.x;                 // 0..6399
    int b = bi / N_NODE, i = bi % N_NODE;
    int t = threadIdx.x;                 // 256
    __shared__ uint8_t sj[256];
    float acc = 0.f;
    for (int r = 0; r < N_REL; r++) {
        int br = b * N_REL + r;
        int c = cnt[br * N_NODE + i];
        const uint8_t* base = nbr + ((size_t)br * N_NODE + i) * N_NODE;
        if (t < c) sj[t] = base[t];
        __syncthreads();
        if (t < C_DIM) {
            const float* yb = y + (size_t)b * N_NODE * RC + (size_t)r * C_DIM + t;
            float tmp = 0.f;
            #pragma unroll 4
            for (int s = 0; s < c; s++)
                tmp += yb[(size_t)sj[s] * RC];
            acc += tmp * (1.0f / (float)c);
        }
        __syncthreads();
    }
    if (t < C_DIM) xout[(size_t)bi * C_DIM + t] = gelu_f(acc);
}

// ---------------------------------------------------------------------------
// Attention pooling: one block per b. Writes pool_attn into d_out and graph_vecs.
// ---------------------------------------------------------------------------
__global__ void k_attn(const float* __restrict__ q, const float* __restrict__ ks,
                       const float* __restrict__ vs, const int* __restrict__ lens,
                       float* __restrict__ out, float* __restrict__ gv) {
    int b = blockIdx.x;
    int t = threadIdx.x;   // 256
    __shared__ float sq[C_DIM];
    __shared__ float sa[2][N_NODE];
    __shared__ float red[256];
    if (t < C_DIM) sq[t] = q[b * C_DIM + t];
    __syncthreads();
    int len = lens[b];
    for (int h = 0; h < 2; h++) {
        float s = -INFINITY;
        if (t < N_NODE && t < len) {
            float acc = 0.f;
            const float* kr = ks + ((size_t)(b * N_NODE + t)) * C_DIM + h * 100;
            #pragma unroll 4
            for (int d = 0; d < 100; d++) acc += sq[h * 100 + d] * kr[d];
            s = acc * 0.1f;   // / sqrt(dk=100)
        }
        red[t] = s;
        __syncthreads();
        for (int off = 128; off > 0; off >>= 1) {
            if (t < off) red[t] = fmaxf(red[t], red[t + off]);
            __syncthreads();
        }
        float mx = red[0];
        __syncthreads();
        float e = (t < N_NODE && t < len) ? expf(s - mx) : 0.f;
        red[t] = e;
        __syncthreads();
        for (int off = 128; off > 0; off >>= 1) {
            if (t < off) red[t] += red[t + off];
            __syncthreads();
        }
        float inv = 1.f / red[0];
        __syncthreads();
        if (t < N_NODE) {
            float a = e * inv;
            sa[h][t] = a;
            out[32 + ((size_t)(h * B_ + b)) * N_NODE + t] = a;
        }
        __syncthreads();
    }
    if (t < C_DIM) {
        int h = t / 100, d = t % 100;
        float g = 0.f;
        for (int l = 0; l < N_NODE; l++)
            g += sa[h][l] * vs[((size_t)(b * N_NODE + l)) * C_DIM + h * 100 + d];
        gv[b * C_DIM + t] = g;
    }
}

// ---------------------------------------------------------------------------
// MLP readout: one block (512 threads) per b.
// ---------------------------------------------------------------------------
__global__ void k_mlp(const float* __restrict__ gv, const float* __restrict__ sent,
                      const float* __restrict__ W0, const float* __restrict__ b0,
                      const float* __restrict__ lng, const float* __restrict__ lnb,
                      const float* __restrict__ W1, const float* __restrict__ b1,
                      float* __restrict__ out) {
    int b = blockIdx.x;
    int t = threadIdx.x;   // 512
    const int ZD = C_DIM + SENT_DIM;   // 1224
    __shared__ float zz[C_DIM + SENT_DIM];
    __shared__ float red[512];
    for (int i = t; i < ZD; i += 512)
        zz[i] = (i < C_DIM) ? gv[b * C_DIM + i] : sent[(size_t)b * SENT_DIM + (i - C_DIM)];
    __syncthreads();
    float acc = b0[t];
    #pragma unroll 4
    for (int k = 0; k < ZD; k++) acc += zz[k] * W0[(size_t)k * FC_DIM + t];
    red[t] = acc; __syncthreads();
    for (int off = 256; off > 0; off >>= 1) { if (t < off) red[t] += red[t + off]; __syncthreads(); }
    float mu = red[0] * (1.f / FC_DIM);
    __syncthreads();
    float d = acc - mu;
    red[t] = d * d; __syncthreads();
    for (int off = 256; off > 0; off >>= 1) { if (t < off) red[t] += red[t + off]; __syncthreads(); }
    float var = red[0] * (1.f / FC_DIM);
    __syncthreads();
    float h1 = gelu_f(d * rsqrtf(var + 1e-5f) * lng[t] + lnb[t]);
    red[t] = h1 * W1[t]; __syncthreads();
    for (int off = 256; off > 0; off >>= 1) { if (t < off) red[t] += red[t + off]; __syncthreads(); }
    if (t == 0) out[b] = red[0] + b1[0];
}

// ---------------------------------------------------------------------------
extern "C" void kernel_launch(void* const* d_in, const int* in_sizes, int n_in,
                              void* d_out, int out_size) {
    const float* sent     = (const float*)d_in[0];
    const int*   concepts = (const int*)  d_in[1];
    const float* adj      = (const float*)d_in[2];
    const int*   lens     = (const int*)  d_in[3];
    const float* emb      = (const float*)d_in[4];
    const float* cptW     = (const float*)d_in[5];
    const float* cptb     = (const float*)d_in[6];
    const float* gnnw     = (const float*)d_in[7];
    const float* wq       = (const float*)d_in[8];
    const float* bq       = (const float*)d_in[9];
    const float* wk       = (const float*)d_in[10];
    const float* bk       = (const float*)d_in[11];
    const float* wv       = (const float*)d_in[12];
    const float* bv       = (const float*)d_in[13];
    const float* fcW0     = (const float*)d_in[14];
    const float* fcb0     = (const float*)d_in[15];
    const float* lng      = (const float*)d_in[16];
    const float* lnb      = (const float*)d_in[17];
    const float* fcW1     = (const float*)d_in[18];
    const float* fcb1     = (const float*)d_in[19];
    float* out = (float*)d_out;

    float *px, *px2, *py, *pw2, *pk, *pv, *pq, *pgv;
    uint8_t* pnbr; int* pcnt;
    cudaGetSymbolAddress((void**)&px,   g_x);
    cudaGetSymbolAddress((void**)&px2,  g_x2);
    cudaGetSymbolAddress((void**)&py,   g_y);
    cudaGetSymbolAddress((void**)&pw2,  g_W2);
    cudaGetSymbolAddress((void**)&pnbr, g_nbr);
    cudaGetSymbolAddress((void**)&pcnt, g_cnt);
    cudaGetSymbolAddress((void**)&pk,   g_k);
    cudaGetSymbolAddress((void**)&pv,   g_v);
    cudaGetSymbolAddress((void**)&pq,   g_q);
    cudaGetSymbolAddress((void**)&pgv,  g_gv);

    // sparse structure + weight permute
    k_build<<<NBR_, 256>>>(adj, pnbr, pcnt);
    k_w2t<<<3 * C_DIM, 256>>>(gnnw, pw2);

    // embedding: x = gelu(emb[concepts] @ cpt_W + cpt_b)   (M=6400, K=1024, N=200)
    {
        dim3 g((C_DIM + 127) / 128, (ROWS + 63) / 64);
        k_gemm<true, true><<<g, 256>>>(emb, concepts, C_IN, cptW, C_DIM, cptb,
                                       px, C_DIM, ROWS, C_DIM, C_IN);
    }

    // 3 RGCN layers: y = x @ W2[l]  (M=6400, N=6800, K=200), then sparse aggregate
    dim3 gY((RC + 127) / 128, (ROWS + 63) / 64);
    const size_t LW = (size_t)C_DIM * RC;
    k_gemm<false, false><<<gY, 256>>>(px, nullptr, C_DIM, pw2 + 0 * LW, RC, nullptr,
                                      py, RC, ROWS, RC, C_DIM);
    k_sagg<<<ROWS, 256>>>(py, pnbr, pcnt, px2);
    k_gemm<false, false><<<gY, 256>>>(px2, nullptr, C_DIM, pw2 + 1 * LW, RC, nullptr,
                                      py, RC, ROWS, RC, C_DIM);
    k_sagg<<<ROWS, 256>>>(py, pnbr, pcnt, px);
    k_gemm<false, false><<<gY, 256>>>(px, nullptr, C_DIM, pw2 + 2 * LW, RC, nullptr,
                                      py, RC, ROWS, RC, C_DIM);
    k_sagg<<<ROWS, 256>>>(py, pnbr, pcnt, px2);   // final x in px2

    // q = sent @ wq + bq  (M=32, K=1024, N=200)
    {
        dim3 g((C_DIM + 127) / 128, (B_ + 63) / 64);
        k_gemm<false, true><<<g, 256>>>(sent, nullptr, SENT_DIM, wq, C_DIM, bq,
                                        pq, C_DIM, B_, C_DIM, SENT_DIM);
    }
    // k/v = x @ wk/wv + b  (M=6400, K=200, N=200)
    {
        dim3 g((C_DIM + 127) / 128, (ROWS + 63) / 64);
        k_gemm<false, true><<<g, 256>>>(px2, nullptr, C_DIM, wk, C_DIM, bk,
                                        pk, C_DIM, ROWS, C_DIM, C_DIM);
        k_gemm<false, true><<<g, 256>>>(px2, nullptr, C_DIM, wv, C_DIM, bv,
                                        pv, C_DIM, ROWS, C_DIM, C_DIM);
    }

    // attention pooling (writes pool_attn part of out) + graph_vecs
    k_attn<<<B_, 256>>>(pq, pk, pv, lens, out, pgv);

    // MLP readout (writes logits part of out)
    k_mlp<<<B_, 512>>>(pgv, sent, fcW0, fcb0, lng, lnb, fcW1, fcb1, out);
}

// round 5
// speedup vs baseline: 2.6415x; 1.8804x over previous
#include <cuda_runtime.h>
#include <math.h>
#include <stdint.h>

#define B_        32
#define N_NODE    200
#define N_REL     34
#define C_DIM     200
#define C_IN      1024
#define SENT_DIM  1024
#define FC_DIM    512
#define NBR_      (B_ * N_REL)            /* 1088 */
#define NN        (N_NODE * N_NODE)       /* 40000 */
#define RC        (N_REL * C_DIM)         /* 6800 */
#define ROWS      (B_ * N_NODE)           /* 6400 */

// -------- device scratch (no allocations allowed) --------
__device__ float   g_x  [ROWS * C_DIM];
__device__ float   g_x2 [ROWS * C_DIM];
__device__ float   g_y  [(size_t)ROWS * RC];    // 174 MB: y[b*200+j][r*200+o]
__device__ float   g_W2 [3 * C_DIM * RC];       // W2[l][c][r*200+o]
__device__ uint8_t g_nbr[(size_t)NBR_ * N_NODE * N_NODE];
__device__ int     g_cnt[NBR_ * N_NODE];
__device__ float   g_k  [ROWS * C_DIM];
__device__ float   g_v  [ROWS * C_DIM];
__device__ float   g_q  [B_ * C_DIM];
__device__ float   g_gv [B_ * C_DIM];

__device__ __forceinline__ float gelu_f(float x) {
    return 0.5f * x * (1.0f + erff(x * 0.70710678118654752f));
}

// ---------------------------------------------------------------------------
// Build in-edge lists: nbr[br][i][*] = { j : adj[br][j][i] != 0 },  cnt = count.
// ---------------------------------------------------------------------------
__global__ void k_build(const float* __restrict__ adj, uint8_t* __restrict__ nbr,
                        int* __restrict__ cnt) {
    int br = blockIdx.x;
    int i = threadIdx.x;
    if (i < N_NODE) {
        const float* a = adj + (size_t)br * NN + i;
        uint8_t* nb = nbr + ((size_t)br * N_NODE + i) * N_NODE;
        int c = 0;
        for (int j = 0; j < N_NODE; j++)
            if (a[(size_t)j * N_NODE] != 0.f) nb[c++] = (uint8_t)j;
        cnt[br * N_NODE + i] = c;
    }
}

// ---------------------------------------------------------------------------
// Permute gnn_w rows: w2[l][c][r*200+o] = gw[l][c][o*34+r].
// ---------------------------------------------------------------------------
__global__ void k_w2t(const float* __restrict__ gw, float* __restrict__ w2) {
    __shared__ float s[RC];
    int lc = blockIdx.x;
    const float* src = gw + (size_t)lc * RC;
    float* dst = w2 + (size_t)lc * RC;
    for (int idx = threadIdx.x; idx < RC; idx += 256) s[idx] = src[idx];
    __syncthreads();
    for (int n = threadIdx.x; n < RC; n += 256) {
        int r = n / C_DIM, o = n % C_DIM;
        dst[n] = s[o * N_REL + r];
    }
}

// ---------------------------------------------------------------------------
// Tiled GEMM: C[M,N] = act(A[M,K] @ B[K,N] + bias), A optionally row-gathered.
// 128x128x16 tiles, 256 threads, 8x8 microtiles split into 4-wide halves at
// +0/+64 so every LDS.128 phase is either a broadcast (A) or 16 consecutive
// float4 covering banks 0..31 once (B) — conflict-free.
// Requires K % 8 == 0, N % 4 == 0 (holds at all call sites).
// ---------------------------------------------------------------------------
template <bool GELU, bool BIAS>
__global__ void __launch_bounds__(256, 2)
k_gemm(const float* __restrict__ A, const int* __restrict__ gather, int lda,
       const float* __restrict__ Bm, int ldb, const float* __restrict__ bias,
       float* __restrict__ C, int ldc, int M, int N, int K) {
    __shared__ __align__(16) float sA[16][132];   // [k][m] (132*4B, 16B-aligned rows)
    __shared__ __align__(16) float sB[16][128];   // [k][n]
    const int t = threadIdx.x;
    const int n0 = blockIdx.x * 128, m0 = blockIdx.y * 128;

    // loader coords
    const int rowA = t >> 1, kqA = (t & 1) * 8;
    const int kkB = t >> 4, nqB = (t & 15) * 4;
    // compute coords
    const int tr4 = (t >> 4) * 4, tc4 = (t & 15) * 4;

    const int gm = m0 + rowA;
    const float* arow = nullptr;
    if (gm < M) arow = A + (size_t)(gather ? gather[gm] : gm) * lda;
    const bool bn0 = (n0 + nqB) < N;
    const bool bn1 = (n0 + 64 + nqB) < N;

    const float4 z4 = make_float4(0.f, 0.f, 0.f, 0.f);
    float4 aR0 = z4, aR1 = z4, bR0 = z4, bR1 = z4;

    // prefetch stage 0
    {
        int ka = kqA;
        if (arow && ka < K) {
            aR0 = *reinterpret_cast<const float4*>(arow + ka);
            aR1 = *reinterpret_cast<const float4*>(arow + ka + 4);
        }
        int kb = kkB;
        if (kb < K) {
            const float* bp = Bm + (size_t)kb * ldb + n0 + nqB;
            if (bn0) bR0 = *reinterpret_cast<const float4*>(bp);
            if (bn1) bR1 = *reinterpret_cast<const float4*>(bp + 64);
        }
    }

    float acc[8][8] = {};
    for (int k0 = 0; k0 < K; k0 += 16) {
        __syncthreads();
        sA[kqA + 0][rowA] = aR0.x; sA[kqA + 1][rowA] = aR0.y;
        sA[kqA + 2][rowA] = aR0.z; sA[kqA + 3][rowA] = aR0.w;
        sA[kqA + 4][rowA] = aR1.x; sA[kqA + 5][rowA] = aR1.y;
        sA[kqA + 6][rowA] = aR1.z; sA[kqA + 7][rowA] = aR1.w;
        *reinterpret_cast<float4*>(&sB[kkB][nqB])      = bR0;
        *reinterpret_cast<float4*>(&sB[kkB][64 + nqB]) = bR1;

        // prefetch next stage
        int k1 = k0 + 16;
        if (k1 < K) {
            aR0 = z4; aR1 = z4; bR0 = z4; bR1 = z4;
            int ka = k1 + kqA;
            if (arow && ka < K) {
                aR0 = *reinterpret_cast<const float4*>(arow + ka);
                aR1 = *reinterpret_cast<const float4*>(arow + ka + 4);
            }
            int kb = k1 + kkB;
            if (kb < K) {
                const float* bp = Bm + (size_t)kb * ldb + n0 + nqB;
                if (bn0) bR0 = *reinterpret_cast<const float4*>(bp);
                if (bn1) bR1 = *reinterpret_cast<const float4*>(bp + 64);
            }
        }
        __syncthreads();

        #pragma unroll
        for (int kk = 0; kk < 16; kk++) {
            float4 a0 = *reinterpret_cast<const float4*>(&sA[kk][tr4]);
            float4 a1 = *reinterpret_cast<const float4*>(&sA[kk][64 + tr4]);
            float4 b0 = *reinterpret_cast<const float4*>(&sB[kk][tc4]);
            float4 b1 = *reinterpret_cast<const float4*>(&sB[kk][64 + tc4]);
            const float av[8] = {a0.x, a0.y, a0.z, a0.w, a1.x, a1.y, a1.z, a1.w};
            const float bv[8] = {b0.x, b0.y, b0.z, b0.w, b1.x, b1.y, b1.z, b1.w};
            #pragma unroll
            for (int i = 0; i < 8; i++)
                #pragma unroll
                for (int j = 0; j < 8; j++)
                    acc[i][j] += av[i] * bv[j];
        }
    }

    #pragma unroll
    for (int i = 0; i < 8; i++) {
        int m = m0 + ((i < 4) ? (tr4 + i) : (64 + tr4 + i - 4));
        if (m >= M) continue;
        #pragma unroll
        for (int jh = 0; jh < 2; jh++) {
            int n = n0 + jh * 64 + tc4;
            if (n >= N) continue;
            float4 v;
            v.x = acc[i][jh * 4 + 0]; v.y = acc[i][jh * 4 + 1];
            v.z = acc[i][jh * 4 + 2]; v.w = acc[i][jh * 4 + 3];
            if (BIAS) {
                v.x += bias[n + 0]; v.y += bias[n + 1];
                v.z += bias[n + 2]; v.w += bias[n + 3];
            }
            if (GELU) {
                v.x = gelu_f(v.x); v.y = gelu_f(v.y);
                v.z = gelu_f(v.z); v.w = gelu_f(v.w);
            }
            *reinterpret_cast<float4*>(&C[(size_t)m * ldc + n]) = v;
        }
    }
}

// ---------------------------------------------------------------------------
// Sparse aggregate + GELU (float4, 64 threads, 50 active lanes):
// xout[b,i,o] = gelu( sum_r (1/cnt) * sum_{j in nbr(b,r,i)} y[b,j, r*200+o] )
// ---------------------------------------------------------------------------
__global__ void k_sagg(const float* __restrict__ y, const uint8_t* __restrict__ nbr,
                       const int* __restrict__ cnt, float* __restrict__ xout) {
    int bi = blockIdx.x;                 // 0..6399
    int b = bi / N_NODE, i = bi % N_NODE;
    int t = threadIdx.x;                 // 64
    __shared__ uint8_t sj[N_NODE];
    float4 acc = make_float4(0.f, 0.f, 0.f, 0.f);
    const float* yb = y + (size_t)b * N_NODE * RC;
    for (int r = 0; r < N_REL; r++) {
        int br = b * N_REL + r;
        int c = cnt[br * N_NODE + i];
        const uint8_t* base = nbr + ((size_t)br * N_NODE + i) * N_NODE;
        for (int s = t; s < c; s += 64) sj[s] = base[s];
        __syncthreads();
        if (t < 50) {
            const float* yr = yb + r * C_DIM + t * 4;
            float4 tmp = make_float4(0.f, 0.f, 0.f, 0.f);
            #pragma unroll 4
            for (int s = 0; s < c; s++) {
                float4 v = *reinterpret_cast<const float4*>(yr + (size_t)sj[s] * RC);
                tmp.x += v.x; tmp.y += v.y; tmp.z += v.z; tmp.w += v.w;
            }
            float inv = 1.0f / (float)c;
            acc.x += tmp.x * inv; acc.y += tmp.y * inv;
            acc.z += tmp.z * inv; acc.w += tmp.w * inv;
        }
        __syncthreads();
    }
    if (t < 50) {
        float4 o;
        o.x = gelu_f(acc.x); o.y = gelu_f(acc.y);
        o.z = gelu_f(acc.z); o.w = gelu_f(acc.w);
        *reinterpret_cast<float4*>(&xout[(size_t)bi * C_DIM + t * 4]) = o;
    }
}

// ---------------------------------------------------------------------------
// Attention pooling: one block per b. Writes pool_attn into d_out and graph_vecs.
// ---------------------------------------------------------------------------
__global__ void k_attn(const float* __restrict__ q, const float* __restrict__ ks,
                       const float* __restrict__ vs, const int* __restrict__ lens,
                       float* __restrict__ out, float* __restrict__ gv) {
    int b = blockIdx.x;
    int t = threadIdx.x;   // 256
    __shared__ float sq[C_DIM];
    __shared__ float sa[2][N_NODE];
    __shared__ float red[256];
    if (t < C_DIM) sq[t] = q[b * C_DIM + t];
    __syncthreads();
    int len = lens[b];
    for (int h = 0; h < 2; h++) {
        float s = -INFINITY;
        if (t < N_NODE && t < len) {
            float acc = 0.f;
            const float* kr = ks + ((size_t)(b * N_NODE + t)) * C_DIM + h * 100;
            #pragma unroll 4
            for (int d = 0; d < 100; d++) acc += sq[h * 100 + d] * kr[d];
            s = acc * 0.1f;
        }
        red[t] = s;
        __syncthreads();
        for (int off = 128; off > 0; off >>= 1) {
            if (t < off) red[t] = fmaxf(red[t], red[t + off]);
            __syncthreads();
        }
        float mx = red[0];
        __syncthreads();
        float e = (t < N_NODE && t < len) ? expf(s - mx) : 0.f;
        red[t] = e;
        __syncthreads();
        for (int off = 128; off > 0; off >>= 1) {
            if (t < off) red[t] += red[t + off];
            __syncthreads();
        }
        float inv = 1.f / red[0];
        __syncthreads();
        if (t < N_NODE) {
            float a = e * inv;
            sa[h][t] = a;
            out[32 + ((size_t)(h * B_ + b)) * N_NODE + t] = a;
        }
        __syncthreads();
    }
    if (t < C_DIM) {
        int h = t / 100, d = t % 100;
        float g = 0.f;
        for (int l = 0; l < N_NODE; l++)
            g += sa[h][l] * vs[((size_t)(b * N_NODE + l)) * C_DIM + h * 100 + d];
        gv[b * C_DIM + t] = g;
    }
}

// ---------------------------------------------------------------------------
// MLP readout: one block (512 threads) per b.
// ---------------------------------------------------------------------------
__global__ void k_mlp(const float* __restrict__ gv, const float* __restrict__ sent,
                      const float* __restrict__ W0, const float* __restrict__ b0,
                      const float* __restrict__ lng, const float* __restrict__ lnb,
                      const float* __restrict__ W1, const float* __restrict__ b1,
                      float* __restrict__ out) {
    int b = blockIdx.x;
    int t = threadIdx.x;   // 512
    const int ZD = C_DIM + SENT_DIM;   // 1224
    __shared__ float zz[C_DIM + SENT_DIM];
    __shared__ float red[512];
    for (int i = t; i < ZD; i += 512)
        zz[i] = (i < C_DIM) ? gv[b * C_DIM + i] : sent[(size_t)b * SENT_DIM + (i - C_DIM)];
    __syncthreads();
    float acc = b0[t];
    #pragma unroll 4
    for (int k = 0; k < ZD; k++) acc += zz[k] * W0[(size_t)k * FC_DIM + t];
    red[t] = acc; __syncthreads();
    for (int off = 256; off > 0; off >>= 1) { if (t < off) red[t] += red[t + off]; __syncthreads(); }
    float mu = red[0] * (1.f / FC_DIM);
    __syncthreads();
    float d = acc - mu;
    red[t] = d * d; __syncthreads();
    for (int off = 256; off > 0; off >>= 1) { if (t < off) red[t] += red[t + off]; __syncthreads(); }
    float var = red[0] * (1.f / FC_DIM);
    __syncthreads();
    float h1 = gelu_f(d * rsqrtf(var + 1e-5f) * lng[t] + lnb[t]);
    red[t] = h1 * W1[t]; __syncthreads();
    for (int off = 256; off > 0; off >>= 1) { if (t < off) red[t] += red[t + off]; __syncthreads(); }
    if (t == 0) out[b] = red[0] + b1[0];
}

// ---------------------------------------------------------------------------
extern "C" void kernel_launch(void* const* d_in, const int* in_sizes, int n_in,
                              void* d_out, int out_size) {
    const float* sent     = (const float*)d_in[0];
    const int*   concepts = (const int*)  d_in[1];
    const float* adj      = (const float*)d_in[2];
    const int*   lens     = (const int*)  d_in[3];
    const float* emb      = (const float*)d_in[4];
    const float* cptW     = (const float*)d_in[5];
    const float* cptb     = (const float*)d_in[6];
    const float* gnnw     = (const float*)d_in[7];
    const float* wq       = (const float*)d_in[8];
    const float* bq       = (const float*)d_in[9];
    const float* wk       = (const float*)d_in[10];
    const float* bk       = (const float*)d_in[11];
    const float* wv       = (const float*)d_in[12];
    const float* bv       = (const float*)d_in[13];
    const float* fcW0     = (const float*)d_in[14];
    const float* fcb0     = (const float*)d_in[15];
    const float* lng      = (const float*)d_in[16];
    const float* lnb      = (const float*)d_in[17];
    const float* fcW1     = (const float*)d_in[18];
    const float* fcb1     = (const float*)d_in[19];
    float* out = (float*)d_out;

    float *px, *px2, *py, *pw2, *pk, *pv, *pq, *pgv;
    uint8_t* pnbr; int* pcnt;
    cudaGetSymbolAddress((void**)&px,   g_x);
    cudaGetSymbolAddress((void**)&px2,  g_x2);
    cudaGetSymbolAddress((void**)&py,   g_y);
    cudaGetSymbolAddress((void**)&pw2,  g_W2);
    cudaGetSymbolAddress((void**)&pnbr, g_nbr);
    cudaGetSymbolAddress((void**)&pcnt, g_cnt);
    cudaGetSymbolAddress((void**)&pk,   g_k);
    cudaGetSymbolAddress((void**)&pv,   g_v);
    cudaGetSymbolAddress((void**)&pq,   g_q);
    cudaGetSymbolAddress((void**)&pgv,  g_gv);

    // sparse structure + weight permute
    k_build<<<NBR_, 256>>>(adj, pnbr, pcnt);
    k_w2t<<<3 * C_DIM, 256>>>(gnnw, pw2);

    // embedding: x = gelu(emb[concepts] @ cpt_W + cpt_b)   (M=6400, K=1024, N=200)
    {
        dim3 g((C_DIM + 127) / 128, (ROWS + 127) / 128);
        k_gemm<true, true><<<g, 256>>>(emb, concepts, C_IN, cptW, C_DIM, cptb,
                                       px, C_DIM, ROWS, C_DIM, C_IN);
    }

    // 3 RGCN layers: y = x @ W2[l]  (M=6400, N=6800, K=200), then sparse aggregate
    dim3 gY((RC + 127) / 128, (ROWS + 127) / 128);
    const size_t LW = (size_t)C_DIM * RC;
    k_gemm<false, false><<<gY, 256>>>(px, nullptr, C_DIM, pw2 + 0 * LW, RC, nullptr,
                                      py, RC, ROWS, RC, C_DIM);
    k_sagg<<<ROWS, 64>>>(py, pnbr, pcnt, px2);
    k_gemm<false, false><<<gY, 256>>>(px2, nullptr, C_DIM, pw2 + 1 * LW, RC, nullptr,
                                      py, RC, ROWS, RC, C_DIM);
    k_sagg<<<ROWS, 64>>>(py, pnbr, pcnt, px);
    k_gemm<false, false><<<gY, 256>>>(px, nullptr, C_DIM, pw2 + 2 * LW, RC, nullptr,
                                      py, RC, ROWS, RC, C_DIM);
    k_sagg<<<ROWS, 64>>>(py, pnbr, pcnt, px2);   // final x in px2

    // q = sent @ wq + bq  (M=32, K=1024, N=200)
    {
        dim3 g((C_DIM + 127) / 128, 1);
        k_gemm<false, true><<<g, 256>>>(sent, nullptr, SENT_DIM, wq, C_DIM, bq,
                                        pq, C_DIM, B_, C_DIM, SENT_DIM);
    }
    // k/v = x @ wk/wv + b  (M=6400, K=200, N=200)
    {
        dim3 g((C_DIM + 127) / 128, (ROWS + 127) / 128);
        k_gemm<false, true><<<g, 256>>>(px2, nullptr, C_DIM, wk, C_DIM, bk,
                                        pk, C_DIM, ROWS, C_DIM, C_DIM);
        k_gemm<false, true><<<g, 256>>>(px2, nullptr, C_DIM, wv, C_DIM, bv,
                                        pv, C_DIM, ROWS, C_DIM, C_DIM);
    }

    // attention pooling (writes pool_attn part of out) + graph_vecs
    k_attn<<<B_, 256>>>(pq, pk, pv, lens, out, pgv);

    // MLP readout (writes logits part of out)
    k_mlp<<<B_, 512>>>(pgv, sent, fcW0, fcb0, lng, lnb, fcW1, fcb1, out);
}

// round 11
// speedup vs baseline: 3.1455x; 1.1908x over previous
#include <cuda_runtime.h>
#include <cuda_bf16.h>
#include <math.h>
#include <stdint.h>

#define B_        32
#define N_NODE    200
#define N_REL     34
#define C_DIM     200
#define C_IN      1024
#define SENT_DIM  1024
#define FC_DIM    512
#define NBR_      (B_ * N_REL)            /* 1088 */
#define NN        (N_NODE * N_NODE)       /* 40000 */
#define RC        (N_REL * C_DIM)         /* 6800 */
#define ROWS      (B_ * N_NODE)           /* 6400 */
#define KP        224                     /* padded K for tensor path (7 x 32) */
#define WT_L      (KP * RC)               /* bf16 elems of W per layer */

// -------- device scratch (no allocations allowed) --------
__device__ float   g_x  [ROWS * C_DIM];
__device__ float   g_x2 [ROWS * C_DIM];
__device__ float   g_y  [(size_t)ROWS * RC];    // 174 MB
__device__ float   g_W2 [3 * C_DIM * RC];       // W2[l][k][n] fp32
__device__ uint8_t g_nbr[(size_t)NBR_ * N_NODE * N_NODE];
__device__ int     g_cnt[NBR_ * N_NODE];
__device__ float   g_k  [ROWS * C_DIM];
__device__ float   g_v  [ROWS * C_DIM];
__device__ float   g_q  [B_ * C_DIM];
__device__ float   g_gv [B_ * C_DIM];
// tensor-core operands (split bf16)
__device__ __nv_bfloat16 g_xhi[ROWS * KP];
__device__ __nv_bfloat16 g_xlo[ROWS * KP];
__device__ __nv_bfloat16 g_whi[3 * WT_L];
__device__ __nv_bfloat16 g_wlo[3 * WT_L];

__device__ __forceinline__ float gelu_f(float x) {
    return 0.5f * x * (1.0f + erff(x * 0.70710678118654752f));
}

__device__ __forceinline__ uint32_t smem_u32(const void* p) {
    uint32_t a;
    asm("{ .reg .u64 t; cvta.to.shared.u64 t, %1; cvt.u32.u64 %0, t; }" : "=r"(a) : "l"(p));
    return a;
}
__device__ __forceinline__ void ldsm4(uint32_t* r, uint32_t addr) {
    asm volatile("ldmatrix.sync.aligned.m8n8.x4.shared.b16 {%0,%1,%2,%3}, [%4];"
                 : "=r"(r[0]), "=r"(r[1]), "=r"(r[2]), "=r"(r[3]) : "r"(addr));
}
__device__ __forceinline__ void ldsm4t(uint32_t* r, uint32_t addr) {
    asm volatile("ldmatrix.sync.aligned.m8n8.x4.trans.shared.b16 {%0,%1,%2,%3}, [%4];"
                 : "=r"(r[0]), "=r"(r[1]), "=r"(r[2]), "=r"(r[3]) : "r"(addr));
}
__device__ __forceinline__ void mma16816(float* c, const uint32_t* a, const uint32_t* b) {
    asm volatile(
        "mma.sync.aligned.m16n8k16.row.col.f32.bf16.bf16.f32 "
        "{%0,%1,%2,%3}, {%4,%5,%6,%7}, {%8,%9}, {%0,%1,%2,%3};"
        : "+f"(c[0]), "+f"(c[1]), "+f"(c[2]), "+f"(c[3])
        : "r"(a[0]), "r"(a[1]), "r"(a[2]), "r"(a[3]), "r"(b[0]), "r"(b[1]));
}

// ---------------------------------------------------------------------------
// Build in-edge lists.
// ---------------------------------------------------------------------------
__global__ void k_build(const float* __restrict__ adj, uint8_t* __restrict__ nbr,
                        int* __restrict__ cnt) {
    int br = blockIdx.x;
    int i = threadIdx.x;
    if (i < N_NODE) {
        const float* a = adj + (size_t)br * NN + i;
        uint8_t* nb = nbr + ((size_t)br * N_NODE + i) * N_NODE;
        int c = 0;
        for (int j = 0; j < N_NODE; j++)
            if (a[(size_t)j * N_NODE] != 0.f) nb[c++] = (uint8_t)j;
        cnt[br * N_NODE + i] = c;
    }
}

// ---------------------------------------------------------------------------
// Permute gnn_w: w2[l][k][r*200+o] = gw[l][k][o*34+r].
// ---------------------------------------------------------------------------
__global__ void k_w2t(const float* __restrict__ gw, float* __restrict__ w2) {
    __shared__ float s[RC];
    int lc = blockIdx.x;
    const float* src = gw + (size_t)lc * RC;
    float* dst = w2 + (size_t)lc * RC;
    for (int idx = threadIdx.x; idx < RC; idx += 256) s[idx] = src[idx];
    __syncthreads();
    for (int n = threadIdx.x; n < RC; n += 256) {
        int r = n / C_DIM, o = n % C_DIM;
        dst[n] = s[o * N_REL + r];
    }
}

// ---------------------------------------------------------------------------
// Split W2 fp32 [l][200][6800] -> bf16 hi/lo [l][224][6800], K rows >=200 zero.
// ---------------------------------------------------------------------------
__global__ void k_wsplit(const float* __restrict__ w2,
                         __nv_bfloat16* __restrict__ hi, __nv_bfloat16* __restrict__ lo) {
    size_t idx = (size_t)blockIdx.x * 256 + threadIdx.x;
    if (idx >= (size_t)3 * WT_L) return;
    int l = (int)(idx / WT_L);
    int rem = (int)(idx % WT_L);
    int k = rem / RC, n = rem % RC;
    float v = (k < C_DIM) ? w2[((size_t)l * C_DIM + k) * RC + n] : 0.f;
    __nv_bfloat16 h = __float2bfloat16(v);
    hi[idx] = h;
    lo[idx] = __float2bfloat16(v - __bfloat162float(h));
}

// ---------------------------------------------------------------------------
// Split x fp32 [ROWS][200] -> bf16 hi/lo [ROWS][224] zero-padded.
// (Used once, after the embedding GEMM; later layers get hi/lo from k_sagg.)
// ---------------------------------------------------------------------------
__global__ void k_split(const float* __restrict__ x,
                        __nv_bfloat16* __restrict__ hi, __nv_bfloat16* __restrict__ lo) {
    int idx = blockIdx.x * 256 + threadIdx.x;
    if (idx >= ROWS * KP) return;
    int row = idx / KP, k = idx % KP;
    float v = (k < C_DIM) ? x[row * C_DIM + k] : 0.f;
    __nv_bfloat16 h = __float2bfloat16(v);
    hi[idx] = h;
    lo[idx] = __float2bfloat16(v - __bfloat162float(h));
}

// ---------------------------------------------------------------------------
// Layer GEMM on tensor cores (mma.sync bf16, split-precision 3-pass):
// y[m][n] = sum_k x[m][k] * W[k][n]   (M=6400, N=6800, K=200)
// 128x128 CTA tile, 8 warps (2M x 4N), each warp 64x32 via m16n8k16.
// Virtual K loop: 3 passes (Ah*Bh, Ah*Bl, Al*Bh) x 7 chunks of k32.
// ---------------------------------------------------------------------------
__global__ void __launch_bounds__(256)
k_mma(const __nv_bfloat16* __restrict__ xhi, const __nv_bfloat16* __restrict__ xlo,
      const __nv_bfloat16* __restrict__ whi, const __nv_bfloat16* __restrict__ wlo,
      float* __restrict__ y) {
    __shared__ __align__(16) __nv_bfloat16 sA[128][40];    // k-chunk 32, +8 pad
    __shared__ __align__(16) __nv_bfloat16 sB[32][136];    // n 128, +8 pad
    const int t = threadIdx.x;
    const int lane = t & 31, wid = t >> 5;
    const int wm = (wid & 1) * 64, wn = (wid >> 1) * 32;
    const int m0 = blockIdx.y * 128, n0 = blockIdx.x * 128;

    // global loader coords
    const int arow = t >> 1, acol = (t & 1) * 16;    // A: 2 x 16B per thread
    const int brow = t >> 3, bcol = (t & 7) * 16;    // B: 2 x 16B per thread
    const bool bg0 = (n0 + bcol) < RC;
    const bool bg1 = (n0 + bcol + 8) < RC;

    // ldmatrix smem addresses (bytes)
    const uint32_t sa_b = smem_u32(&sA[0][0]);
    const uint32_t sb_b = smem_u32(&sB[0][0]);
    uint32_t saAddr[4], sbAddr[2];
    #pragma unroll
    for (int mi = 0; mi < 4; mi++)
        saAddr[mi] = sa_b + ((wm + mi * 16 + (lane & 15)) * 40 + (lane >> 4) * 8) * 2;
    #pragma unroll
    for (int nb = 0; nb < 2; nb++)
        sbAddr[nb] = sb_b + ((lane & 15) * 136 + wn + nb * 16 + (lane >> 4) * 8) * 2;

    float acc[4][4][4];
    #pragma unroll
    for (int i = 0; i < 4; i++)
        #pragma unroll
        for (int j = 0; j < 4; j++)
            #pragma unroll
            for (int q = 0; q < 4; q++) acc[i][j][q] = 0.f;

    const uint4 z4 = make_uint4(0, 0, 0, 0);
    uint4 aP0, aP1, bP0, bP1;

    // prefetch chunk 0
    {
        const __nv_bfloat16* ar = xhi + (size_t)(m0 + arow) * KP + acol;
        aP0 = *reinterpret_cast<const uint4*>(ar);
        aP1 = *reinterpret_cast<const uint4*>(ar + 8);
        const __nv_bfloat16* br = whi + (size_t)brow * RC + n0 + bcol;
        bP0 = bg0 ? *reinterpret_cast<const uint4*>(br) : z4;
        bP1 = bg1 ? *reinterpret_cast<const uint4*>(br + 8) : z4;
    }

    for (int it = 0; it < 21; it++) {
        __syncthreads();
        *reinterpret_cast<uint4*>(&sA[arow][acol])     = aP0;
        *reinterpret_cast<uint4*>(&sA[arow][acol + 8]) = aP1;
        *reinterpret_cast<uint4*>(&sB[brow][bcol])     = bP0;
        *reinterpret_cast<uint4*>(&sB[brow][bcol + 8]) = bP1;

        if (it + 1 < 21) {
            int p = (it + 1) / 7, kc = ((it + 1) % 7) * 32;
            const __nv_bfloat16* Ap = (p < 2) ? xhi : xlo;
            const __nv_bfloat16* Bp = (p == 1) ? wlo : whi;
            const __nv_bfloat16* ar = Ap + (size_t)(m0 + arow) * KP + kc + acol;
            aP0 = *reinterpret_cast<const uint4*>(ar);
            aP1 = *reinterpret_cast<const uint4*>(ar + 8);
            const __nv_bfloat16* br = Bp + (size_t)(kc + brow) * RC + n0 + bcol;
            bP0 = bg0 ? *reinterpret_cast<const uint4*>(br) : z4;
            bP1 = bg1 ? *reinterpret_cast<const uint4*>(br + 8) : z4;
        }
        __syncthreads();

        #pragma unroll
        for (int ks = 0; ks < 2; ks++) {
            uint32_t bf[8];
            ldsm4t(bf,     sbAddr[0] + ks * 4352);   // 16 rows * 272B
            ldsm4t(bf + 4, sbAddr[1] + ks * 4352);
            uint32_t af[4][4];
            #pragma unroll
            for (int mi = 0; mi < 4; mi++)
                ldsm4(af[mi], saAddr[mi] + ks * 32);
            #pragma unroll
            for (int mi = 0; mi < 4; mi++) {
                mma16816(acc[mi][0], af[mi], bf + 0);
                mma16816(acc[mi][1], af[mi], bf + 2);
                mma16816(acc[mi][2], af[mi], bf + 4);
                mma16816(acc[mi][3], af[mi], bf + 6);
            }
        }
    }

    // epilogue: c-frag rows = lane>>2 (+8), cols = (lane&3)*2 (+1)
    #pragma unroll
    for (int mi = 0; mi < 4; mi++) {
        int r = m0 + wm + mi * 16 + (lane >> 2);
        #pragma unroll
        for (int nj = 0; nj < 4; nj++) {
            int c = n0 + wn + nj * 8 + (lane & 3) * 2;
            if (c < RC) {
                *reinterpret_cast<float2*>(&y[(size_t)r * RC + c]) =
                    make_float2(acc[mi][nj][0], acc[mi][nj][1]);
                *reinterpret_cast<float2*>(&y[(size_t)(r + 8) * RC + c]) =
                    make_float2(acc[mi][nj][2], acc[mi][nj][3]);
            }
        }
    }
}

// ---------------------------------------------------------------------------
// fp32 tiled GEMM (emb / q / k / v): 128x128x16, 8x8 microtiles, conflict-free.
// ---------------------------------------------------------------------------
template <bool GELU, bool BIAS>
__global__ void __launch_bounds__(256, 2)
k_gemm(const float* __restrict__ A, const int* __restrict__ gather, int lda,
       const float* __restrict__ Bm, int ldb, const float* __restrict__ bias,
       float* __restrict__ C, int ldc, int M, int N, int K) {
    __shared__ __align__(16) float sA[16][132];
    __shared__ __align__(16) float sB[16][128];
    const int t = threadIdx.x;
    const int n0 = blockIdx.x * 128, m0 = blockIdx.y * 128;
    const int rowA = t >> 1, kqA = (t & 1) * 8;
    const int kkB = t >> 4, nqB = (t & 15) * 4;
    const int tr4 = (t >> 4) * 4, tc4 = (t & 15) * 4;

    const int gm = m0 + rowA;
    const float* arow = nullptr;
    if (gm < M) arow = A + (size_t)(gather ? gather[gm] : gm) * lda;
    const bool bn0 = (n0 + nqB) < N;
    const bool bn1 = (n0 + 64 + nqB) < N;

    const float4 z4 = make_float4(0.f, 0.f, 0.f, 0.f);
    float4 aR0 = z4, aR1 = z4, bR0 = z4, bR1 = z4;
    {
        int ka = kqA;
        if (arow && ka < K) {
            aR0 = *reinterpret_cast<const float4*>(arow + ka);
            aR1 = *reinterpret_cast<const float4*>(arow + ka + 4);
        }
        int kb = kkB;
        if (kb < K) {
            const float* bp = Bm + (size_t)kb * ldb + n0 + nqB;
            if (bn0) bR0 = *reinterpret_cast<const float4*>(bp);
            if (bn1) bR1 = *reinterpret_cast<const float4*>(bp + 64);
        }
    }

    float acc[8][8] = {};
    for (int k0 = 0; k0 < K; k0 += 16) {
        __syncthreads();
        sA[kqA + 0][rowA] = aR0.x; sA[kqA + 1][rowA] = aR0.y;
        sA[kqA + 2][rowA] = aR0.z; sA[kqA + 3][rowA] = aR0.w;
        sA[kqA + 4][rowA] = aR1.x; sA[kqA + 5][rowA] = aR1.y;
        sA[kqA + 6][rowA] = aR1.z; sA[kqA + 7][rowA] = aR1.w;
        *reinterpret_cast<float4*>(&sB[kkB][nqB])      = bR0;
        *reinterpret_cast<float4*>(&sB[kkB][64 + nqB]) = bR1;

        int k1 = k0 + 16;
        if (k1 < K) {
            aR0 = z4; aR1 = z4; bR0 = z4; bR1 = z4;
            int ka = k1 + kqA;
            if (arow && ka < K) {
                aR0 = *reinterpret_cast<const float4*>(arow + ka);
                aR1 = *reinterpret_cast<const float4*>(arow + ka + 4);
            }
            int kb = k1 + kkB;
            if (kb < K) {
                const float* bp = Bm + (size_t)kb * ldb + n0 + nqB;
                if (bn0) bR0 = *reinterpret_cast<const float4*>(bp);
                if (bn1) bR1 = *reinterpret_cast<const float4*>(bp + 64);
            }
        }
        __syncthreads();

        #pragma unroll
        for (int kk = 0; kk < 16; kk++) {
            float4 a0 = *reinterpret_cast<const float4*>(&sA[kk][tr4]);
            float4 a1 = *reinterpret_cast<const float4*>(&sA[kk][64 + tr4]);
            float4 b0 = *reinterpret_cast<const float4*>(&sB[kk][tc4]);
            float4 b1 = *reinterpret_cast<const float4*>(&sB[kk][64 + tc4]);
            const float av[8] = {a0.x, a0.y, a0.z, a0.w, a1.x, a1.y, a1.z, a1.w};
            const float bv[8] = {b0.x, b0.y, b0.z, b0.w, b1.x, b1.y, b1.z, b1.w};
            #pragma unroll
            for (int i = 0; i < 8; i++)
                #pragma unroll
                for (int j = 0; j < 8; j++)
                    acc[i][j] += av[i] * bv[j];
        }
    }

    #pragma unroll
    for (int i = 0; i < 8; i++) {
        int m = m0 + ((i < 4) ? (tr4 + i) : (64 + tr4 + i - 4));
        if (m >= M) continue;
        #pragma unroll
        for (int jh = 0; jh < 2; jh++) {
            int n = n0 + jh * 64 + tc4;
            if (n >= N) continue;
            float4 v;
            v.x = acc[i][jh * 4 + 0]; v.y = acc[i][jh * 4 + 1];
            v.z = acc[i][jh * 4 + 2]; v.w = acc[i][jh * 4 + 3];
            if (BIAS) {
                v.x += bias[n + 0]; v.y += bias[n + 1];
                v.z += bias[n + 2]; v.w += bias[n + 3];
            }
            if (GELU) {
                v.x = gelu_f(v.x); v.y = gelu_f(v.y);
                v.z = gelu_f(v.z); v.w = gelu_f(v.w);
            }
            *reinterpret_cast<float4*>(&C[(size_t)m * ldc + n]) = v;
        }
    }
}

// ---------------------------------------------------------------------------
// Sparse aggregate + GELU, fused with bf16 hi/lo split for the next layer.
// xout fp32 [ROWS][200]; hi/lo bf16 [ROWS][224] (threads 50..55 zero the pad).
// ---------------------------------------------------------------------------
__global__ void k_sagg(const float* __restrict__ y, const uint8_t* __restrict__ nbr,
                       const int* __restrict__ cnt, float* __restrict__ xout,
                       __nv_bfloat16* __restrict__ hi, __nv_bfloat16* __restrict__ lo) {
    int bi = blockIdx.x;
    int b = bi / N_NODE, i = bi % N_NODE;
    int t = threadIdx.x;                 // 64
    __shared__ uint8_t sj[N_NODE];
    float4 acc = make_float4(0.f, 0.f, 0.f, 0.f);
    const float* yb = y + (size_t)b * N_NODE * RC;
    for (int r = 0; r < N_REL; r++) {
        int br = b * N_REL + r;
        int c = cnt[br * N_NODE + i];
        const uint8_t* base = nbr + ((size_t)br * N_NODE + i) * N_NODE;
        for (int s = t; s < c; s += 64) sj[s] = base[s];
        __syncthreads();
        if (t < 50) {
            const float* yr = yb + r * C_DIM + t * 4;
            float4 tmp = make_float4(0.f, 0.f, 0.f, 0.f);
            #pragma unroll 4
            for (int s = 0; s < c; s++) {
                float4 v = *reinterpret_cast<const float4*>(yr + (size_t)sj[s] * RC);
                tmp.x += v.x; tmp.y += v.y; tmp.z += v.z; tmp.w += v.w;
            }
            float inv = 1.0f / (float)c;
            acc.x += tmp.x * inv; acc.y += tmp.y * inv;
            acc.z += tmp.z * inv; acc.w += tmp.w * inv;
        }
        __syncthreads();
    }
    if (t < 50) {
        float o[4];
        o[0] = gelu_f(acc.x); o[1] = gelu_f(acc.y);
        o[2] = gelu_f(acc.z); o[3] = gelu_f(acc.w);
        *reinterpret_cast<float4*>(&xout[(size_t)bi * C_DIM + t * 4]) =
            make_float4(o[0], o[1], o[2], o[3]);
        __align__(8) __nv_bfloat16 h4[4], l4[4];
        #pragma unroll
        for (int j = 0; j < 4; j++) {
            __nv_bfloat16 h = __float2bfloat16(o[j]);
            h4[j] = h;
            l4[j] = __float2bfloat16(o[j] - __bfloat162float(h));
        }
        *reinterpret_cast<uint2*>(&hi[(size_t)bi * KP + t * 4]) = *reinterpret_cast<const uint2*>(h4);
        *reinterpret_cast<uint2*>(&lo[(size_t)bi * KP + t * 4]) = *reinterpret_cast<const uint2*>(l4);
    } else if (t < 56) {
        int col = C_DIM + (t - 50) * 4;   // 200..220, zero the K pad
        uint2 z = make_uint2(0, 0);
        *reinterpret_cast<uint2*>(&hi[(size_t)bi * KP + col]) = z;
        *reinterpret_cast<uint2*>(&lo[(size_t)bi * KP + col]) = z;
    }
}

// ---------------------------------------------------------------------------
// Attention pooling.
// ---------------------------------------------------------------------------
__global__ void k_attn(const float* __restrict__ q, const float* __restrict__ ks,
                       const float* __restrict__ vs, const int* __restrict__ lens,
                       float* __restrict__ out, float* __restrict__ gv) {
    int b = blockIdx.x;
    int t = threadIdx.x;   // 256
    __shared__ float sq[C_DIM];
    __shared__ float sa[2][N_NODE];
    __shared__ float red[256];
    if (t < C_DIM) sq[t] = q[b * C_DIM + t];
    __syncthreads();
    int len = lens[b];
    for (int h = 0; h < 2; h++) {
        float s = -INFINITY;
        if (t < N_NODE && t < len) {
            float acc = 0.f;
            const float* kr = ks + ((size_t)(b * N_NODE + t)) * C_DIM + h * 100;
            #pragma unroll 4
            for (int d = 0; d < 100; d++) acc += sq[h * 100 + d] * kr[d];
            s = acc * 0.1f;
        }
        red[t] = s;
        __syncthreads();
        for (int off = 128; off > 0; off >>= 1) {
            if (t < off) red[t] = fmaxf(red[t], red[t + off]);
            __syncthreads();
        }
        float mx = red[0];
        __syncthreads();
        float e = (t < N_NODE && t < len) ? expf(s - mx) : 0.f;
        red[t] = e;
        __syncthreads();
        for (int off = 128; off > 0; off >>= 1) {
            if (t < off) red[t] += red[t + off];
            __syncthreads();
        }
        float inv = 1.f / red[0];
        __syncthreads();
        if (t < N_NODE) {
            float a = e * inv;
            sa[h][t] = a;
            out[32 + ((size_t)(h * B_ + b)) * N_NODE + t] = a;
        }
        __syncthreads();
    }
    if (t < C_DIM) {
        int h = t / 100, d = t % 100;
        float g = 0.f;
        for (int l = 0; l < N_NODE; l++)
            g += sa[h][l] * vs[((size_t)(b * N_NODE + l)) * C_DIM + h * 100 + d];
        gv[b * C_DIM + t] = g;
    }
}

// ---------------------------------------------------------------------------
// MLP readout.
// ---------------------------------------------------------------------------
__global__ void k_mlp(const float* __restrict__ gv, const float* __restrict__ sent,
                      const float* __restrict__ W0, const float* __restrict__ b0,
                      const float* __restrict__ lng, const float* __restrict__ lnb,
                      const float* __restrict__ W1, const float* __restrict__ b1,
                      float* __restrict__ out) {
    int b = blockIdx.x;
    int t = threadIdx.x;   // 512
    const int ZD = C_DIM + SENT_DIM;
    __shared__ float zz[C_DIM + SENT_DIM];
    __shared__ float red[512];
    for (int i = t; i < ZD; i += 512)
        zz[i] = (i < C_DIM) ? gv[b * C_DIM + i] : sent[(size_t)b * SENT_DIM + (i - C_DIM)];
    __syncthreads();
    float acc = b0[t];
    #pragma unroll 4
    for (int k = 0; k < ZD; k++) acc += zz[k] * W0[(size_t)k * FC_DIM + t];
    red[t] = acc; __syncthreads();
    for (int off = 256; off > 0; off >>= 1) { if (t < off) red[t] += red[t + off]; __syncthreads(); }
    float mu = red[0] * (1.f / FC_DIM);
    __syncthreads();
    float d = acc - mu;
    red[t] = d * d; __syncthreads();
    for (int off = 256; off > 0; off >>= 1) { if (t < off) red[t] += red[t + off]; __syncthreads(); }
    float var = red[0] * (1.f / FC_DIM);
    __syncthreads();
    float h1 = gelu_f(d * rsqrtf(var + 1e-5f) * lng[t] + lnb[t]);
    red[t] = h1 * W1[t]; __syncthreads();
    for (int off = 256; off > 0; off >>= 1) { if (t < off) red[t] += red[t + off]; __syncthreads(); }
    if (t == 0) out[b] = red[0] + b1[0];
}

// ---------------------------------------------------------------------------
extern "C" void kernel_launch(void* const* d_in, const int* in_sizes, int n_in,
                              void* d_out, int out_size) {
    const float* sent     = (const float*)d_in[0];
    const int*   concepts = (const int*)  d_in[1];
    const float* adj      = (const float*)d_in[2];
    const int*   lens     = (const int*)  d_in[3];
    const float* emb      = (const float*)d_in[4];
    const float* cptW     = (const float*)d_in[5];
    const float* cptb     = (const float*)d_in[6];
    const float* gnnw     = (const float*)d_in[7];
    const float* wq       = (const float*)d_in[8];
    const float* bq       = (const float*)d_in[9];
    const float* wk       = (const float*)d_in[10];
    const float* bk       = (const float*)d_in[11];
    const float* wv       = (const float*)d_in[12];
    const float* bv       = (const float*)d_in[13];
    const float* fcW0     = (const float*)d_in[14];
    const float* fcb0     = (const float*)d_in[15];
    const float* lng      = (const float*)d_in[16];
    const float* lnb      = (const float*)d_in[17];
    const float* fcW1     = (const float*)d_in[18];
    const float* fcb1     = (const float*)d_in[19];
    float* out = (float*)d_out;

    float *px, *px2, *py, *pw2, *pk, *pv, *pq, *pgv;
    __nv_bfloat16 *pxhi, *pxlo, *pwhi, *pwlo;
    uint8_t* pnbr; int* pcnt;
    cudaGetSymbolAddress((void**)&px,   g_x);
    cudaGetSymbolAddress((void**)&px2,  g_x2);
    cudaGetSymbolAddress((void**)&py,   g_y);
    cudaGetSymbolAddress((void**)&pw2,  g_W2);
    cudaGetSymbolAddress((void**)&pnbr, g_nbr);
    cudaGetSymbolAddress((void**)&pcnt, g_cnt);
    cudaGetSymbolAddress((void**)&pk,   g_k);
    cudaGetSymbolAddress((void**)&pv,   g_v);
    cudaGetSymbolAddress((void**)&pq,   g_q);
    cudaGetSymbolAddress((void**)&pgv,  g_gv);
    cudaGetSymbolAddress((void**)&pxhi, g_xhi);
    cudaGetSymbolAddress((void**)&pxlo, g_xlo);
    cudaGetSymbolAddress((void**)&pwhi, g_whi);
    cudaGetSymbolAddress((void**)&pwlo, g_wlo);

    // sparse structure + weight permute + split
    k_build<<<NBR_, 256>>>(adj, pnbr, pcnt);
    k_w2t<<<3 * C_DIM, 256>>>(gnnw, pw2);
    {
        size_t nel = (size_t)3 * WT_L;
        k_wsplit<<<(int)((nel + 255) / 256), 256>>>(pw2, pwhi, pwlo);
    }

    // embedding (fp32 path)
    {
        dim3 g((C_DIM + 127) / 128, (ROWS + 127) / 128);
        k_gemm<true, true><<<g, 256>>>(emb, concepts, C_IN, cptW, C_DIM, cptb,
                                       px, C_DIM, ROWS, C_DIM, C_IN);
    }

    // 3 RGCN layers: mma.sync GEMM -> fused sparse aggregate + split
    dim3 gMMA((RC + 127) / 128, ROWS / 128);   // 54 x 50
    k_split<<<(ROWS * KP + 255) / 256, 256>>>(px, pxhi, pxlo);
    k_mma<<<gMMA, 256>>>(pxhi, pxlo, pwhi + (size_t)0 * WT_L, pwlo + (size_t)0 * WT_L, py);
    k_sagg<<<ROWS, 64>>>(py, pnbr, pcnt, px2, pxhi, pxlo);
    k_mma<<<gMMA, 256>>>(pxhi, pxlo, pwhi + (size_t)1 * WT_L, pwlo + (size_t)1 * WT_L, py);
    k_sagg<<<ROWS, 64>>>(py, pnbr, pcnt, px, pxhi, pxlo);
    k_mma<<<gMMA, 256>>>(pxhi, pxlo, pwhi + (size_t)2 * WT_L, pwlo + (size_t)2 * WT_L, py);
    k_sagg<<<ROWS, 64>>>(py, pnbr, pcnt, px2, pxhi, pxlo);   // final x in px2

    // q = sent @ wq + bq
    {
        dim3 g((C_DIM + 127) / 128, 1);
        k_gemm<false, true><<<g, 256>>>(sent, nullptr, SENT_DIM, wq, C_DIM, bq,
                                        pq, C_DIM, B_, C_DIM, SENT_DIM);
    }
    // k/v = x @ wk/wv + b
    {
        dim3 g((C_DIM + 127) / 128, (ROWS + 127) / 128);
        k_gemm<false, true><<<g, 256>>>(px2, nullptr, C_DIM, wk, C_DIM, bk,
                                        pk, C_DIM, ROWS, C_DIM, C_DIM);
        k_gemm<false, true><<<g, 256>>>(px2, nullptr, C_DIM, wv, C_DIM, bv,
                                        pv, C_DIM, ROWS, C_DIM, C_DIM);
    }

    k_attn<<<B_, 256>>>(pq, pk, pv, lens, out, pgv);
    k_mlp<<<B_, 512>>>(pgv, sent, fcW0, fcb0, lng, lnb, fcW1, fcb1, out);
}

// round 12
// speedup vs baseline: 3.2280x; 1.0262x over previous
#include <cuda_runtime.h>
#include <cuda_bf16.h>
#include <math.h>
#include <stdint.h>

#define B_        32
#define N_NODE    200
#define N_REL     34
#define C_DIM     200
#define C_IN      1024
#define SENT_DIM  1024
#define FC_DIM    512
#define NBR_      (B_ * N_REL)            /* 1088 */
#define NN        (N_NODE * N_NODE)       /* 40000 */
#define RC        (N_REL * C_DIM)         /* 6800 */
#define ROWS      (B_ * N_NODE)           /* 6400 */
#define KP        224                     /* padded K for layer/kv tensor path */
#define WT_L      (KP * RC)               /* bf16 elems of layer W per layer */

// -------- device scratch (no allocations allowed) --------
__device__ float   g_x  [ROWS * C_DIM];
__device__ float   g_x2 [ROWS * C_DIM];
__device__ float   g_y  [(size_t)ROWS * RC];    // 174 MB
__device__ float   g_W2 [3 * C_DIM * RC];       // W2[l][k][n] fp32
__device__ uint8_t g_nbr[(size_t)NBR_ * N_NODE * N_NODE];
__device__ int     g_cnt[NBR_ * N_NODE];
__device__ float   g_kv [ROWS * 400];           // fused k|v
__device__ float   g_q  [B_ * C_DIM];
__device__ float   g_gv [B_ * C_DIM];
// tensor-core operands (split bf16)
__device__ __nv_bfloat16 g_xhi[ROWS * KP];
__device__ __nv_bfloat16 g_xlo[ROWS * KP];
__device__ __nv_bfloat16 g_whi[3 * WT_L];
__device__ __nv_bfloat16 g_wlo[3 * WT_L];
__device__ __nv_bfloat16 g_ehi[ROWS * C_IN];    // gathered emb rows, split
__device__ __nv_bfloat16 g_elo[ROWS * C_IN];
__device__ __nv_bfloat16 g_cwhi[C_IN * C_DIM];  // cptW split
__device__ __nv_bfloat16 g_cwlo[C_IN * C_DIM];
__device__ __nv_bfloat16 g_wkvhi[KP * 400];     // [wk|wv] split, K padded
__device__ __nv_bfloat16 g_wkvlo[KP * 400];
__device__ float   g_bkv[400];

__device__ __forceinline__ float gelu_f(float x) {
    return 0.5f * x * (1.0f + erff(x * 0.70710678118654752f));
}

__device__ __forceinline__ uint32_t smem_u32(const void* p) {
    uint32_t a;
    asm("{ .reg .u64 t; cvta.to.shared.u64 t, %1; cvt.u32.u64 %0, t; }" : "=r"(a) : "l"(p));
    return a;
}
__device__ __forceinline__ void ldsm4(uint32_t* r, uint32_t addr) {
    asm volatile("ldmatrix.sync.aligned.m8n8.x4.shared.b16 {%0,%1,%2,%3}, [%4];"
                 : "=r"(r[0]), "=r"(r[1]), "=r"(r[2]), "=r"(r[3]) : "r"(addr));
}
__device__ __forceinline__ void ldsm4t(uint32_t* r, uint32_t addr) {
    asm volatile("ldmatrix.sync.aligned.m8n8.x4.trans.shared.b16 {%0,%1,%2,%3}, [%4];"
                 : "=r"(r[0]), "=r"(r[1]), "=r"(r[2]), "=r"(r[3]) : "r"(addr));
}
__device__ __forceinline__ void mma16816(float* c, const uint32_t* a, const uint32_t* b) {
    asm volatile(
        "mma.sync.aligned.m16n8k16.row.col.f32.bf16.bf16.f32 "
        "{%0,%1,%2,%3}, {%4,%5,%6,%7}, {%8,%9}, {%0,%1,%2,%3};"
        : "+f"(c[0]), "+f"(c[1]), "+f"(c[2]), "+f"(c[3])
        : "r"(a[0]), "r"(a[1]), "r"(a[2]), "r"(a[3]), "r"(b[0]), "r"(b[1]));
}

// ---------------------------------------------------------------------------
// Build in-edge lists.
// ---------------------------------------------------------------------------
__global__ void k_build(const float* __restrict__ adj, uint8_t* __restrict__ nbr,
                        int* __restrict__ cnt) {
    int br = blockIdx.x;
    int i = threadIdx.x;
    if (i < N_NODE) {
        const float* a = adj + (size_t)br * NN + i;
        uint8_t* nb = nbr + ((size_t)br * N_NODE + i) * N_NODE;
        int c = 0;
        for (int j = 0; j < N_NODE; j++)
            if (a[(size_t)j * N_NODE] != 0.f) nb[c++] = (uint8_t)j;
        cnt[br * N_NODE + i] = c;
    }
}

// ---------------------------------------------------------------------------
// Permute gnn_w: w2[l][k][r*200+o] = gw[l][k][o*34+r].
// ---------------------------------------------------------------------------
__global__ void k_w2t(const float* __restrict__ gw, float* __restrict__ w2) {
    __shared__ float s[RC];
    int lc = blockIdx.x;
    const float* src = gw + (size_t)lc * RC;
    float* dst = w2 + (size_t)lc * RC;
    for (int idx = threadIdx.x; idx < RC; idx += 256) s[idx] = src[idx];
    __syncthreads();
    for (int n = threadIdx.x; n < RC; n += 256) {
        int r = n / C_DIM, o = n % C_DIM;
        dst[n] = s[o * N_REL + r];
    }
}

// ---------------------------------------------------------------------------
// Split W2 fp32 [l][200][6800] -> bf16 hi/lo [l][224][6800], K rows >=200 zero.
// ---------------------------------------------------------------------------
__global__ void k_wsplit(const float* __restrict__ w2,
                         __nv_bfloat16* __restrict__ hi, __nv_bfloat16* __restrict__ lo) {
    size_t idx = (size_t)blockIdx.x * 256 + threadIdx.x;
    if (idx >= (size_t)3 * WT_L) return;
    int l = (int)(idx / WT_L);
    int rem = (int)(idx % WT_L);
    int k = rem / RC, n = rem % RC;
    float v = (k < C_DIM) ? w2[((size_t)l * C_DIM + k) * RC + n] : 0.f;
    __nv_bfloat16 h = __float2bfloat16(v);
    hi[idx] = h;
    lo[idx] = __float2bfloat16(v - __bfloat162float(h));
}

// ---------------------------------------------------------------------------
// Split cptW fp32 [1024][200] -> bf16 hi/lo (no padding; K=1024 = 32*32).
// ---------------------------------------------------------------------------
__global__ void k_cwsplit(const float* __restrict__ w,
                          __nv_bfloat16* __restrict__ hi, __nv_bfloat16* __restrict__ lo) {
    int idx = blockIdx.x * 256 + threadIdx.x;
    if (idx >= C_IN * C_DIM) return;
    float v = w[idx];
    __nv_bfloat16 h = __float2bfloat16(v);
    hi[idx] = h;
    lo[idx] = __float2bfloat16(v - __bfloat162float(h));
}

// ---------------------------------------------------------------------------
// Build [wk|wv] split bf16 [224][400]; bias concat.
// ---------------------------------------------------------------------------
__global__ void k_wkvsplit(const float* __restrict__ wk, const float* __restrict__ wv,
                           const float* __restrict__ bk, const float* __restrict__ bv,
                           __nv_bfloat16* __restrict__ hi, __nv_bfloat16* __restrict__ lo,
                           float* __restrict__ bkv) {
    int idx = blockIdx.x * 256 + threadIdx.x;
    if (idx < 400) bkv[idx] = (idx < C_DIM) ? bk[idx] : bv[idx - C_DIM];
    if (idx >= KP * 400) return;
    int k = idx / 400, n = idx % 400;
    float v = 0.f;
    if (k < C_DIM) v = (n < C_DIM) ? wk[k * C_DIM + n] : wv[k * C_DIM + (n - C_DIM)];
    __nv_bfloat16 h = __float2bfloat16(v);
    hi[idx] = h;
    lo[idx] = __float2bfloat16(v - __bfloat162float(h));
}

// ---------------------------------------------------------------------------
// Gather + split emb rows: hi/lo [ROWS][1024] = split(emb[concepts[row]][k]).
// ---------------------------------------------------------------------------
__global__ void k_gsplit(const float* __restrict__ emb, const int* __restrict__ concepts,
                         __nv_bfloat16* __restrict__ hi, __nv_bfloat16* __restrict__ lo) {
    int idx = blockIdx.x * 256 + threadIdx.x;
    if (idx >= ROWS * C_IN) return;
    int row = idx >> 10, k = idx & 1023;
    float v = emb[(size_t)concepts[row] * C_IN + k];
    __nv_bfloat16 h = __float2bfloat16(v);
    hi[idx] = h;
    lo[idx] = __float2bfloat16(v - __bfloat162float(h));
}

// ---------------------------------------------------------------------------
// Zero the K-pad (cols 200..223) of xhi/xlo once; k_sagg maintains it after.
// ---------------------------------------------------------------------------
__global__ void k_padzero(__nv_bfloat16* __restrict__ hi, __nv_bfloat16* __restrict__ lo) {
    int idx = blockIdx.x * 256 + threadIdx.x;
    if (idx >= ROWS * 24) return;
    int row = idx / 24, col = C_DIM + idx % 24;
    hi[(size_t)row * KP + col] = __float2bfloat16(0.f);
    lo[(size_t)row * KP + col] = __float2bfloat16(0.f);
}

// ---------------------------------------------------------------------------
// Generalized tensor-core GEMM (mma.sync bf16, split-precision 3-pass):
// out[m][n] = act(sum_k A[m][k] * W[k][n] + bias)
// 128x128 CTA tile, 8 warps (2M x 4N), each warp 64x32 via m16n8k16.
// KCH = k32-chunks per pass (A row stride = 32*KCH; W row stride = N).
// SPLITOUT: apply GELU and also emit bf16 hi/lo (stride KP) for the next GEMM.
// N must be a multiple of 8; W rows must be 16B-aligned (N*2 % 16 == 0).
// ---------------------------------------------------------------------------
template <int KCH, bool BIAS, bool SPLITOUT>
__global__ void __launch_bounds__(256)
k_mma(const __nv_bfloat16* __restrict__ xhi, const __nv_bfloat16* __restrict__ xlo,
      const __nv_bfloat16* __restrict__ whi, const __nv_bfloat16* __restrict__ wlo,
      const float* __restrict__ bias, float* __restrict__ out, int ldc, int N,
      __nv_bfloat16* __restrict__ ohi, __nv_bfloat16* __restrict__ olo) {
    const int KPA = KCH * 32;
    __shared__ __align__(16) __nv_bfloat16 sA[128][40];    // k-chunk 32, +8 pad
    __shared__ __align__(16) __nv_bfloat16 sB[32][136];    // n 128, +8 pad
    const int t = threadIdx.x;
    const int lane = t & 31, wid = t >> 5;
    const int wm = (wid & 1) * 64, wn = (wid >> 1) * 32;
    const int m0 = blockIdx.y * 128, n0 = blockIdx.x * 128;

    // global loader coords
    const int arow = t >> 1, acol = (t & 1) * 16;    // A: 2 x 16B per thread
    const int brow = t >> 3, bcol = (t & 7) * 16;    // B: 2 x 16B per thread
    const bool bg0 = (n0 + bcol) < N;
    const bool bg1 = (n0 + bcol + 8) < N;

    // ldmatrix smem addresses (bytes)
    const uint32_t sa_b = smem_u32(&sA[0][0]);
    const uint32_t sb_b = smem_u32(&sB[0][0]);
    uint32_t saAddr[4], sbAddr[2];
    #pragma unroll
    for (int mi = 0; mi < 4; mi++)
        saAddr[mi] = sa_b + ((wm + mi * 16 + (lane & 15)) * 40 + (lane >> 4) * 8) * 2;
    #pragma unroll
    for (int nb = 0; nb < 2; nb++)
        sbAddr[nb] = sb_b + ((lane & 15) * 136 + wn + nb * 16 + (lane >> 4) * 8) * 2;

    float acc[4][4][4];
    #pragma unroll
    for (int i = 0; i < 4; i++)
        #pragma unroll
        for (int j = 0; j < 4; j++)
            #pragma unroll
            for (int q = 0; q < 4; q++) acc[i][j][q] = 0.f;

    const uint4 z4 = make_uint4(0, 0, 0, 0);
    uint4 aP0, aP1, bP0, bP1;

    // prefetch chunk 0
    {
        const __nv_bfloat16* ar = xhi + (size_t)(m0 + arow) * KPA + acol;
        aP0 = *reinterpret_cast<const uint4*>(ar);
        aP1 = *reinterpret_cast<const uint4*>(ar + 8);
        const __nv_bfloat16* br = whi + (size_t)brow * N + n0 + bcol;
        bP0 = bg0 ? *reinterpret_cast<const uint4*>(br) : z4;
        bP1 = bg1 ? *reinterpret_cast<const uint4*>(br + 8) : z4;
    }

    const int NITER = 3 * KCH;
    for (int it = 0; it < NITER; it++) {
        __syncthreads();
        *reinterpret_cast<uint4*>(&sA[arow][acol])     = aP0;
        *reinterpret_cast<uint4*>(&sA[arow][acol + 8]) = aP1;
        *reinterpret_cast<uint4*>(&sB[brow][bcol])     = bP0;
        *reinterpret_cast<uint4*>(&sB[brow][bcol + 8]) = bP1;

        if (it + 1 < NITER) {
            int p = (it + 1) / KCH, kc = ((it + 1) % KCH) * 32;
            const __nv_bfloat16* Ap = (p < 2) ? xhi : xlo;
            const __nv_bfloat16* Bp = (p == 1) ? wlo : whi;
            const __nv_bfloat16* ar = Ap + (size_t)(m0 + arow) * KPA + kc + acol;
            aP0 = *reinterpret_cast<const uint4*>(ar);
            aP1 = *reinterpret_cast<const uint4*>(ar + 8);
            const __nv_bfloat16* br = Bp + (size_t)(kc + brow) * N + n0 + bcol;
            bP0 = bg0 ? *reinterpret_cast<const uint4*>(br) : z4;
            bP1 = bg1 ? *reinterpret_cast<const uint4*>(br + 8) : z4;
        }
        __syncthreads();

        #pragma unroll
        for (int ks = 0; ks < 2; ks++) {
            uint32_t bf[8];
            ldsm4t(bf,     sbAddr[0] + ks * 4352);   // 16 rows * 272B
            ldsm4t(bf + 4, sbAddr[1] + ks * 4352);
            uint32_t af[4][4];
            #pragma unroll
            for (int mi = 0; mi < 4; mi++)
                ldsm4(af[mi], saAddr[mi] + ks * 32);
            #pragma unroll
            for (int mi = 0; mi < 4; mi++) {
                mma16816(acc[mi][0], af[mi], bf + 0);
                mma16816(acc[mi][1], af[mi], bf + 2);
                mma16816(acc[mi][2], af[mi], bf + 4);
                mma16816(acc[mi][3], af[mi], bf + 6);
            }
        }
    }

    // epilogue: c-frag rows = lane>>2 (+8), cols = (lane&3)*2 (+1)
    #pragma unroll
    for (int mi = 0; mi < 4; mi++) {
        int r = m0 + wm + mi * 16 + (lane >> 2);
        #pragma unroll
        for (int nj = 0; nj < 4; nj++) {
            int c = n0 + wn + nj * 8 + (lane & 3) * 2;
            if (c < N) {
                #pragma unroll
                for (int half = 0; half < 2; half++) {
                    int rr = r + half * 8;
                    float v0 = acc[mi][nj][half * 2 + 0];
                    float v1 = acc[mi][nj][half * 2 + 1];
                    if (BIAS) { v0 += bias[c]; v1 += bias[c + 1]; }
                    if (SPLITOUT) {
                        v0 = gelu_f(v0); v1 = gelu_f(v1);
                        __align__(4) __nv_bfloat16 h2[2], l2[2];
                        h2[0] = __float2bfloat16(v0);
                        h2[1] = __float2bfloat16(v1);
                        l2[0] = __float2bfloat16(v0 - __bfloat162float(h2[0]));
                        l2[1] = __float2bfloat16(v1 - __bfloat162float(h2[1]));
                        *reinterpret_cast<uint32_t*>(&ohi[(size_t)rr * KP + c]) =
                            *reinterpret_cast<const uint32_t*>(h2);
                        *reinterpret_cast<uint32_t*>(&olo[(size_t)rr * KP + c]) =
                            *reinterpret_cast<const uint32_t*>(l2);
                    }
                    *reinterpret_cast<float2*>(&out[(size_t)rr * ldc + c]) =
                        make_float2(v0, v1);
                }
            }
        }
    }
}

// ---------------------------------------------------------------------------
// fp32 tiled GEMM (q only): 128x128x16, 8x8 microtiles, conflict-free.
// ---------------------------------------------------------------------------
template <bool GELU, bool BIAS>
__global__ void __launch_bounds__(256, 2)
k_gemm(const float* __restrict__ A, const int* __restrict__ gather, int lda,
       const float* __restrict__ Bm, int ldb, const float* __restrict__ bias,
       float* __restrict__ C, int ldc, int M, int N, int K) {
    __shared__ __align__(16) float sA[16][132];
    __shared__ __align__(16) float sB[16][128];
    const int t = threadIdx.x;
    const int n0 = blockIdx.x * 128, m0 = blockIdx.y * 128;
    const int rowA = t >> 1, kqA = (t & 1) * 8;
    const int kkB = t >> 4, nqB = (t & 15) * 4;
    const int tr4 = (t >> 4) * 4, tc4 = (t & 15) * 4;

    const int gm = m0 + rowA;
    const float* arow = nullptr;
    if (gm < M) arow = A + (size_t)(gather ? gather[gm] : gm) * lda;
    const bool bn0 = (n0 + nqB) < N;
    const bool bn1 = (n0 + 64 + nqB) < N;

    const float4 z4 = make_float4(0.f, 0.f, 0.f, 0.f);
    float4 aR0 = z4, aR1 = z4, bR0 = z4, bR1 = z4;
    {
        int ka = kqA;
        if (arow && ka < K) {
            aR0 = *reinterpret_cast<const float4*>(arow + ka);
            aR1 = *reinterpret_cast<const float4*>(arow + ka + 4);
        }
        int kb = kkB;
        if (kb < K) {
            const float* bp = Bm + (size_t)kb * ldb + n0 + nqB;
            if (bn0) bR0 = *reinterpret_cast<const float4*>(bp);
            if (bn1) bR1 = *reinterpret_cast<const float4*>(bp + 64);
        }
    }

    float acc[8][8] = {};
    for (int k0 = 0; k0 < K; k0 += 16) {
        __syncthreads();
        sA[kqA + 0][rowA] = aR0.x; sA[kqA + 1][rowA] = aR0.y;
        sA[kqA + 2][rowA] = aR0.z; sA[kqA + 3][rowA] = aR0.w;
        sA[kqA + 4][rowA] = aR1.x; sA[kqA + 5][rowA] = aR1.y;
        sA[kqA + 6][rowA] = aR1.z; sA[kqA + 7][rowA] = aR1.w;
        *reinterpret_cast<float4*>(&sB[kkB][nqB])      = bR0;
        *reinterpret_cast<float4*>(&sB[kkB][64 + nqB]) = bR1;

        int k1 = k0 + 16;
        if (k1 < K) {
            aR0 = z4; aR1 = z4; bR0 = z4; bR1 = z4;
            int ka = k1 + kqA;
            if (arow && ka < K) {
                aR0 = *reinterpret_cast<const float4*>(arow + ka);
                aR1 = *reinterpret_cast<const float4*>(arow + ka + 4);
            }
            int kb = k1 + kkB;
            if (kb < K) {
                const float* bp = Bm + (size_t)kb * ldb + n0 + nqB;
                if (bn0) bR0 = *reinterpret_cast<const float4*>(bp);
                if (bn1) bR1 = *reinterpret_cast<const float4*>(bp + 64);
            }
        }
        __syncthreads();

        #pragma unroll
        for (int kk = 0; kk < 16; kk++) {
            float4 a0 = *reinterpret_cast<const float4*>(&sA[kk][tr4]);
            float4 a1 = *reinterpret_cast<const float4*>(&sA[kk][64 + tr4]);
            float4 b0 = *reinterpret_cast<const float4*>(&sB[kk][tc4]);
            float4 b1 = *reinterpret_cast<const float4*>(&sB[kk][64 + tc4]);
            const float av[8] = {a0.x, a0.y, a0.z, a0.w, a1.x, a1.y, a1.z, a1.w};
            const float bv[8] = {b0.x, b0.y, b0.z, b0.w, b1.x, b1.y, b1.z, b1.w};
            #pragma unroll
            for (int i = 0; i < 8; i++)
                #pragma unroll
                for (int j = 0; j < 8; j++)
                    acc[i][j] += av[i] * bv[j];
        }
    }

    #pragma unroll
    for (int i = 0; i < 8; i++) {
        int m = m0 + ((i < 4) ? (tr4 + i) : (64 + tr4 + i - 4));
        if (m >= M) continue;
        #pragma unroll
        for (int jh = 0; jh < 2; jh++) {
            int n = n0 + jh * 64 + tc4;
            if (n >= N) continue;
            float4 v;
            v.x = acc[i][jh * 4 + 0]; v.y = acc[i][jh * 4 + 1];
            v.z = acc[i][jh * 4 + 2]; v.w = acc[i][jh * 4 + 3];
            if (BIAS) {
                v.x += bias[n + 0]; v.y += bias[n + 1];
                v.z += bias[n + 2]; v.w += bias[n + 3];
            }
            if (GELU) {
                v.x = gelu_f(v.x); v.y = gelu_f(v.y);
                v.z = gelu_f(v.z); v.w = gelu_f(v.w);
            }
            *reinterpret_cast<float4*>(&C[(size_t)m * ldc + n]) = v;
        }
    }
}

// ---------------------------------------------------------------------------
// Sparse aggregate + GELU, fused with bf16 hi/lo split for the next layer.
// xout fp32 [ROWS][200]; hi/lo bf16 [ROWS][224] (threads 50..55 zero the pad).
// ---------------------------------------------------------------------------
__global__ void k_sagg(const float* __restrict__ y, const uint8_t* __restrict__ nbr,
                       const int* __restrict__ cnt, float* __restrict__ xout,
                       __nv_bfloat16* __restrict__ hi, __nv_bfloat16* __restrict__ lo) {
    int bi = blockIdx.x;
    int b = bi / N_NODE, i = bi % N_NODE;
    int t = threadIdx.x;                 // 64
    __shared__ uint8_t sj[N_NODE];
    float4 acc = make_float4(0.f, 0.f, 0.f, 0.f);
    const float* yb = y + (size_t)b * N_NODE * RC;
    for (int r = 0; r < N_REL; r++) {
        int br = b * N_REL + r;
        int c = cnt[br * N_NODE + i];
        const uint8_t* base = nbr + ((size_t)br * N_NODE + i) * N_NODE;
        for (int s = t; s < c; s += 64) sj[s] = base[s];
        __syncthreads();
        if (t < 50) {
            const float* yr = yb + r * C_DIM + t * 4;
            float4 tmp = make_float4(0.f, 0.f, 0.f, 0.f);
            #pragma unroll 4
            for (int s = 0; s < c; s++) {
                float4 v = *reinterpret_cast<const float4*>(yr + (size_t)sj[s] * RC);
                tmp.x += v.x; tmp.y += v.y; tmp.z += v.z; tmp.w += v.w;
            }
            float inv = 1.0f / (float)c;
            acc.x += tmp.x * inv; acc.y += tmp.y * inv;
            acc.z += tmp.z * inv; acc.w += tmp.w * inv;
        }
        __syncthreads();
    }
    if (t < 50) {
        float o[4];
        o[0] = gelu_f(acc.x); o[1] = gelu_f(acc.y);
        o[2] = gelu_f(acc.z); o[3] = gelu_f(acc.w);
        *reinterpret_cast<float4*>(&xout[(size_t)bi * C_DIM + t * 4]) =
            make_float4(o[0], o[1], o[2], o[3]);
        __align__(8) __nv_bfloat16 h4[4], l4[4];
        #pragma unroll
        for (int j = 0; j < 4; j++) {
            __nv_bfloat16 h = __float2bfloat16(o[j]);
            h4[j] = h;
            l4[j] = __float2bfloat16(o[j] - __bfloat162float(h));
        }
        *reinterpret_cast<uint2*>(&hi[(size_t)bi * KP + t * 4]) = *reinterpret_cast<const uint2*>(h4);
        *reinterpret_cast<uint2*>(&lo[(size_t)bi * KP + t * 4]) = *reinterpret_cast<const uint2*>(l4);
    } else if (t < 56) {
        int col = C_DIM + (t - 50) * 4;   // 200..220, zero the K pad
        uint2 z = make_uint2(0, 0);
        *reinterpret_cast<uint2*>(&hi[(size_t)bi * KP + col]) = z;
        *reinterpret_cast<uint2*>(&lo[(size_t)bi * KP + col]) = z;
    }
}

// ---------------------------------------------------------------------------
// Attention pooling; k/v fused in one buffer with row stride 400 (k@0, v@200).
// ---------------------------------------------------------------------------
__global__ void k_attn(const float* __restrict__ q, const float* __restrict__ kv,
                       const int* __restrict__ lens,
                       float* __restrict__ out, float* __restrict__ gv) {
    int b = blockIdx.x;
    int t = threadIdx.x;   // 256
    __shared__ float sq[C_DIM];
    __shared__ float sa[2][N_NODE];
    __shared__ float red[256];
    if (t < C_DIM) sq[t] = q[b * C_DIM + t];
    __syncthreads();
    int len = lens[b];
    for (int h = 0; h < 2; h++) {
        float s = -INFINITY;
        if (t < N_NODE && t < len) {
            float acc = 0.f;
            const float* kr = kv + ((size_t)(b * N_NODE + t)) * 400 + h * 100;
            #pragma unroll 4
            for (int d = 0; d < 100; d++) acc += sq[h * 100 + d] * kr[d];
            s = acc * 0.1f;
        }
        red[t] = s;
        __syncthreads();
        for (int off = 128; off > 0; off >>= 1) {
            if (t < off) red[t] = fmaxf(red[t], red[t + off]);
            __syncthreads();
        }
        float mx = red[0];
        __syncthreads();
        float e = (t < N_NODE && t < len) ? expf(s - mx) : 0.f;
        red[t] = e;
        __syncthreads();
        for (int off = 128; off > 0; off >>= 1) {
            if (t < off) red[t] += red[t + off];
            __syncthreads();
        }
        float inv = 1.f / red[0];
        __syncthreads();
        if (t < N_NODE) {
            float a = e * inv;
            sa[h][t] = a;
            out[32 + ((size_t)(h * B_ + b)) * N_NODE + t] = a;
        }
        __syncthreads();
    }
    if (t < C_DIM) {
        int h = t / 100, d = t % 100;
        float g = 0.f;
        for (int l = 0; l < N_NODE; l++)
            g += sa[h][l] * kv[((size_t)(b * N_NODE + l)) * 400 + 200 + h * 100 + d];
        gv[b * C_DIM + t] = g;
    }
}

// ---------------------------------------------------------------------------
// MLP readout.
// ---------------------------------------------------------------------------
__global__ void k_mlp(const float* __restrict__ gv, const float* __restrict__ sent,
                      const float* __restrict__ W0, const float* __restrict__ b0,
                      const float* __restrict__ lng, const float* __restrict__ lnb,
                      const float* __restrict__ W1, const float* __restrict__ b1,
                      float* __restrict__ out) {
    int b = blockIdx.x;
    int t = threadIdx.x;   // 512
    const int ZD = C_DIM + SENT_DIM;
    __shared__ float zz[C_DIM + SENT_DIM];
    __shared__ float red[512];
    for (int i = t; i < ZD; i += 512)
        zz[i] = (i < C_DIM) ? gv[b * C_DIM + i] : sent[(size_t)b * SENT_DIM + (i - C_DIM)];
    __syncthreads();
    float acc = b0[t];
    #pragma unroll 4
    for (int k = 0; k < ZD; k++) acc += zz[k] * W0[(size_t)k * FC_DIM + t];
    red[t] = acc; __syncthreads();
    for (int off = 256; off > 0; off >>= 1) { if (t < off) red[t] += red[t + off]; __syncthreads(); }
    float mu = red[0] * (1.f / FC_DIM);
    __syncthreads();
    float d = acc - mu;
    red[t] = d * d; __syncthreads();
    for (int off = 256; off > 0; off >>= 1) { if (t < off) red[t] += red[t + off]; __syncthreads(); }
    float var = red[0] * (1.f / FC_DIM);
    __syncthreads();
    float h1 = gelu_f(d * rsqrtf(var + 1e-5f) * lng[t] + lnb[t]);
    red[t] = h1 * W1[t]; __syncthreads();
    for (int off = 256; off > 0; off >>= 1) { if (t < off) red[t] += red[t + off]; __syncthreads(); }
    if (t == 0) out[b] = red[0] + b1[0];
}

// ---------------------------------------------------------------------------
extern "C" void kernel_launch(void* const* d_in, const int* in_sizes, int n_in,
                              void* d_out, int out_size) {
    const float* sent     = (const float*)d_in[0];
    const int*   concepts = (const int*)  d_in[1];
    const float* adj      = (const float*)d_in[2];
    const int*   lens     = (const int*)  d_in[3];
    const float* emb      = (const float*)d_in[4];
    const float* cptW     = (const float*)d_in[5];
    const float* cptb     = (const float*)d_in[6];
    const float* gnnw     = (const float*)d_in[7];
    const float* wq       = (const float*)d_in[8];
    const float* bq       = (const float*)d_in[9];
    const float* wk       = (const float*)d_in[10];
    const float* bk       = (const float*)d_in[11];
    const float* wv       = (const float*)d_in[12];
    const float* bv       = (const float*)d_in[13];
    const float* fcW0     = (const float*)d_in[14];
    const float* fcb0     = (const float*)d_in[15];
    const float* lng      = (const float*)d_in[16];
    const float* lnb      = (const float*)d_in[17];
    const float* fcW1     = (const float*)d_in[18];
    const float* fcb1     = (const float*)d_in[19];
    float* out = (float*)d_out;

    float *px, *px2, *py, *pw2, *pkv, *pq, *pgv, *pbkv;
    __nv_bfloat16 *pxhi, *pxlo, *pwhi, *pwlo, *pehi, *pelo, *pcwhi, *pcwlo, *pwkvhi, *pwkvlo;
    uint8_t* pnbr; int* pcnt;
    cudaGetSymbolAddress((void**)&px,    g_x);
    cudaGetSymbolAddress((void**)&px2,   g_x2);
    cudaGetSymbolAddress((void**)&py,    g_y);
    cudaGetSymbolAddress((void**)&pw2,   g_W2);
    cudaGetSymbolAddress((void**)&pnbr,  g_nbr);
    cudaGetSymbolAddress((void**)&pcnt,  g_cnt);
    cudaGetSymbolAddress((void**)&pkv,   g_kv);
    cudaGetSymbolAddress((void**)&pq,    g_q);
    cudaGetSymbolAddress((void**)&pgv,   g_gv);
    cudaGetSymbolAddress((void**)&pxhi,  g_xhi);
    cudaGetSymbolAddress((void**)&pxlo,  g_xlo);
    cudaGetSymbolAddress((void**)&pwhi,  g_whi);
    cudaGetSymbolAddress((void**)&pwlo,  g_wlo);
    cudaGetSymbolAddress((void**)&pehi,  g_ehi);
    cudaGetSymbolAddress((void**)&pelo,  g_elo);
    cudaGetSymbolAddress((void**)&pcwhi, g_cwhi);
    cudaGetSymbolAddress((void**)&pcwlo, g_cwlo);
    cudaGetSymbolAddress((void**)&pwkvhi, g_wkvhi);
    cudaGetSymbolAddress((void**)&pwkvlo, g_wkvlo);
    cudaGetSymbolAddress((void**)&pbkv,  g_bkv);

    // prep: sparse structure + all weight splits + gathered emb split
    k_build<<<NBR_, 256>>>(adj, pnbr, pcnt);
    k_w2t<<<3 * C_DIM, 256>>>(gnnw, pw2);
    {
        size_t nel = (size_t)3 * WT_L;
        k_wsplit<<<(int)((nel + 255) / 256), 256>>>(pw2, pwhi, pwlo);
    }
    k_cwsplit<<<(C_IN * C_DIM + 255) / 256, 256>>>(cptW, pcwhi, pcwlo);
    k_wkvsplit<<<(KP * 400 + 255) / 256, 256>>>(wk, wv, bk, bv, pwkvhi, pwkvlo, pbkv);
    k_gsplit<<<(ROWS * C_IN + 255) / 256, 256>>>(emb, concepts, pehi, pelo);
    k_padzero<<<(ROWS * 24 + 255) / 256, 256>>>(pxhi, pxlo);

    // embedding: x = gelu(emb_g @ cptW + cptb) on tensor path; emits x + hi/lo
    {
        dim3 g(2, ROWS / 128);
        k_mma<32, true, true><<<g, 256>>>(pehi, pelo, pcwhi, pcwlo, cptb,
                                          px, C_DIM, C_DIM, pxhi, pxlo);
    }

    // 3 RGCN layers: mma GEMM -> fused sparse aggregate + split
    dim3 gMMA((RC + 127) / 128, ROWS / 128);   // 54 x 50
    k_mma<7, false, false><<<gMMA, 256>>>(pxhi, pxlo, pwhi + (size_t)0 * WT_L,
                                          pwlo + (size_t)0 * WT_L, nullptr, py, RC, RC,
                                          nullptr, nullptr);
    k_sagg<<<ROWS, 64>>>(py, pnbr, pcnt, px2, pxhi, pxlo);
    k_mma<7, false, false><<<gMMA, 256>>>(pxhi, pxlo, pwhi + (size_t)1 * WT_L,
                                          pwlo + (size_t)1 * WT_L, nullptr, py, RC, RC,
                                          nullptr, nullptr);
    k_sagg<<<ROWS, 64>>>(py, pnbr, pcnt, px, pxhi, pxlo);
    k_mma<7, false, false><<<gMMA, 256>>>(pxhi, pxlo, pwhi + (size_t)2 * WT_L,
                                          pwlo + (size_t)2 * WT_L, nullptr, py, RC, RC,
                                          nullptr, nullptr);
    k_sagg<<<ROWS, 64>>>(py, pnbr, pcnt, px2, pxhi, pxlo);   // final x in px2 + hi/lo

    // kv = x @ [wk|wv] + [bk|bv] on tensor path (hi/lo already produced by sagg)
    {
        dim3 g(4, ROWS / 128);
        k_mma<7, true, false><<<g, 256>>>(pxhi, pxlo, pwkvhi, pwkvlo, pbkv,
                                          pkv, 400, 400, nullptr, nullptr);
    }

    // q = sent @ wq + bq (fp32, tiny)
    {
        dim3 g(2, 1);
        k_gemm<false, true><<<g, 256>>>(sent, nullptr, SENT_DIM, wq, C_DIM, bq,
                                        pq, C_DIM, B_, C_DIM, SENT_DIM);
    }

    k_attn<<<B_, 256>>>(pq, pkv, lens, out, pgv);
    k_mlp<<<B_, 512>>>(pgv, sent, fcW0, fcb0, lng, lnb, fcW1, fcb1, out);
}